// round 12
// baseline (speedup 1.0000x reference)
#include <cuda_runtime.h>
#include <cuda_fp16.h>
#include <math.h>
#include <stdint.h>

// Problem constants
constexpr int B_ = 64;
constexpr int T_ = 256;
constexpr int D_ = 512;
constexpr int H_ = 1024;
constexpr int G4 = 4 * H_;         // 4096
constexpr int BH = B_ * H_;        // 65536

// ------------------------- device scratch (no allocs) ----------------------
__device__ float  g_xw[(size_t)B_ * T_ * G4];        // (B*T, 4H) fp32
__device__ float  g_c[BH];                           // cell state fp32
__device__ __half g_h16[2 * BH];                     // double-buffered hidden
__device__ __half g_x16[(size_t)B_ * T_ * D_];
__device__ __half g_W1_16[(size_t)D_ * G4];
__device__ __half g_U1_16[(size_t)H_ * G4];
__device__ __half g_W2_16[(size_t)H_ * G4];
__device__ __half g_U2_16[(size_t)H_ * G4];
__device__ __half g_fc1w16[(size_t)H_ * (H_ / 2)];
__device__ __half g_ys1_16[(size_t)B_ * T_ * H_];
__device__ __half g_ys2_16[(size_t)B_ * T_ * H_];
__device__ float  g_z1[(size_t)B_ * T_ * (H_ / 2)];
__device__ float  g_z2[B_ * 36];
__device__ int    g_cnt[2 * T_ * 2];                 // [layer][t][bh] arrivals

// ------------------------------ PTX helpers --------------------------------
__device__ __forceinline__ uint32_t smem_u32(const void* p) {
    uint32_t a;
    asm("{ .reg .u64 t; cvta.to.shared.u64 t, %1; cvt.u32.u64 %0, t; }"
        : "=r"(a) : "l"(p));
    return a;
}
__device__ __forceinline__ void cp_async16(uint32_t dst, const void* src) {
    asm volatile("cp.async.cg.shared.global [%0], [%1], 16;" :: "r"(dst), "l"(src));
}
__device__ __forceinline__ void cp_commit() {
    asm volatile("cp.async.commit_group;");
}
template <int N> __device__ __forceinline__ void cp_wait_n() {
    asm volatile("cp.async.wait_group %0;" :: "n"(N));
}
__device__ __forceinline__ void ldmatrix_x4(uint32_t* r, uint32_t addr) {
    asm volatile("ldmatrix.sync.aligned.m8n8.x4.shared.b16 {%0,%1,%2,%3}, [%4];"
                 : "=r"(r[0]), "=r"(r[1]), "=r"(r[2]), "=r"(r[3]) : "r"(addr));
}
__device__ __forceinline__ void ldmatrix_x4t(uint32_t* r, uint32_t addr) {
    asm volatile("ldmatrix.sync.aligned.m8n8.x4.trans.shared.b16 {%0,%1,%2,%3}, [%4];"
                 : "=r"(r[0]), "=r"(r[1]), "=r"(r[2]), "=r"(r[3]) : "r"(addr));
}
__device__ __forceinline__ void ldmatrix_x2t(uint32_t* r, uint32_t addr) {
    asm volatile("ldmatrix.sync.aligned.m8n8.x2.trans.shared.b16 {%0,%1}, [%2];"
                 : "=r"(r[0]), "=r"(r[1]) : "r"(addr));
}
__device__ __forceinline__ void mma16816(float* d, const uint32_t* a, const uint32_t* b) {
    asm volatile(
        "mma.sync.aligned.m16n8k16.row.col.f32.f16.f16.f32 "
        "{%0,%1,%2,%3},{%4,%5,%6,%7},{%8,%9},{%0,%1,%2,%3};"
        : "+f"(d[0]), "+f"(d[1]), "+f"(d[2]), "+f"(d[3])
        : "r"(a[0]), "r"(a[1]), "r"(a[2]), "r"(a[3]), "r"(b[0]), "r"(b[1]));
}
// acquire load (volatile asm — cannot be hoisted or deleted)
__device__ __forceinline__ int ld_acquire_gpu(const int* p) {
    int v;
    asm volatile("ld.acquire.gpu.global.s32 %0, [%1];" : "=r"(v) : "l"(p) : "memory");
    return v;
}
// release reduction
__device__ __forceinline__ void red_release_add(int* p, int v) {
    asm volatile("red.release.gpu.global.add.s32 [%0], %1;" :: "l"(p), "r"(v) : "memory");
}

// fast gate math: MUFU-based, rel err ~2e-7 (invisible vs fp16 5.6e-4)
__device__ __forceinline__ float fast_sigmoid(float x) {
    return __fdividef(1.f, 1.f + __expf(-x));
}
__device__ __forceinline__ float fast_tanh(float x) {
    return 1.f - __fdividef(2.f, __expf(2.f * x) + 1.f);
}

// ---------------------------------------------------------------------------
__global__ void f32_to_f16(const float* __restrict__ in, __half* __restrict__ out, int n)
{
    int i4 = (blockIdx.x * 256 + threadIdx.x) * 4;
    if (i4 < n) {
        float4 v = *reinterpret_cast<const float4*>(in + i4);
        *reinterpret_cast<__half2*>(out + i4)     = __floats2half2_rn(v.x, v.y);
        *reinterpret_cast<__half2*>(out + i4 + 2) = __floats2half2_rn(v.z, v.w);
    }
}

// seed h16 buf0 from h0, zero BOTH layers' arrival counters
__global__ void init_all(const float* __restrict__ h0, __half* __restrict__ h16,
                         int* __restrict__ cnt)
{
    int i = blockIdx.x * 256 + threadIdx.x;
    if (i < BH) h16[i] = __float2half_rn(h0[i]);
    if (i < 2 * T_ * 2) cnt[i] = 0;
}

// ---------------------------------------------------------------------------
// HGEMM: C_fp32(M,N) = A_fp16(M,K) @ B_fp16(K,N) + bias(N)
// 128x128x32 tile, 256 threads, THREE-stage cp.async pipeline.
// ---------------------------------------------------------------------------
__global__ void __launch_bounds__(256) hgemm(
    const __half* __restrict__ A, const __half* __restrict__ Bm,
    const float* __restrict__ bias, float* __restrict__ C,
    int M, int N, int K)
{
    __shared__ __half As[3][128 * 40];
    __shared__ __half Bs[3][32 * 136];

    const int tid = threadIdx.x;
    const int w = tid >> 5, lane = tid & 31;
    const int bm = blockIdx.y * 128, bn = blockIdx.x * 128;
    const int wm = (w >> 2) * 64, wn = (w & 3) * 32;
    const uint32_t AsU = smem_u32(As), BsU = smem_u32(Bs);

    float acc[4][4][4];
#pragma unroll
    for (int i = 0; i < 4; i++)
#pragma unroll
        for (int j = 0; j < 4; j++)
#pragma unroll
            for (int e = 0; e < 4; e++) acc[i][j][e] = 0.f;

    const int nk = K / 32;

#define LOAD_TILE(kt, buf)                                                        \
    {                                                                             \
        int k0 = (kt) * 32;                                                       \
        _Pragma("unroll")                                                         \
        for (int e = 0; e < 2; e++) {                                             \
            int idx = tid + e * 256;                                              \
            int r = idx >> 2, ch = idx & 3;                                       \
            cp_async16(AsU + ((buf) * 5120 + r * 40 + ch * 8) * 2,                \
                       A + (size_t)(bm + r) * K + k0 + ch * 8);                   \
        }                                                                         \
        _Pragma("unroll")                                                         \
        for (int e = 0; e < 2; e++) {                                             \
            int idx = tid + e * 256;                                              \
            int r = idx >> 4, ch = idx & 15;                                      \
            cp_async16(BsU + ((buf) * 4352 + r * 136 + ch * 8) * 2,               \
                       Bm + (size_t)(k0 + r) * N + bn + ch * 8);                  \
        }                                                                         \
        cp_commit();                                                              \
    }

    LOAD_TILE(0, 0)
    if (nk > 1) LOAD_TILE(1, 1)

    for (int kt = 0; kt < nk; kt++) {
        int buf = kt % 3;
        if (kt + 1 < nk) cp_wait_n<1>(); else cp_wait_n<0>();
        __syncthreads();
        if (kt + 2 < nk) LOAD_TILE(kt + 2, (kt + 2) % 3)

#pragma unroll
        for (int ks = 0; ks < 2; ks++) {
            uint32_t bfr[4][2];
#pragma unroll
            for (int nf = 0; nf < 4; nf++)
                ldmatrix_x2t(bfr[nf],
                    BsU + (buf * 4352 + (ks * 16 + (lane & 15)) * 136 + wn + nf * 8) * 2);
#pragma unroll
            for (int mf = 0; mf < 4; mf++) {
                uint32_t afr[4];
                ldmatrix_x4(afr,
                    AsU + (buf * 5120 + (wm + mf * 16 + (lane & 15)) * 40
                           + ks * 16 + ((lane >> 4) * 8)) * 2);
#pragma unroll
                for (int nf = 0; nf < 4; nf++) mma16816(acc[mf][nf], afr, bfr[nf]);
            }
        }
        __syncthreads();
    }
#undef LOAD_TILE

    const int g = lane >> 2, t4 = lane & 3;
#pragma unroll
    for (int mf = 0; mf < 4; mf++)
#pragma unroll
        for (int nf = 0; nf < 4; nf++) {
            int row0 = bm + wm + mf * 16 + g;
            int col = bn + wn + nf * 8 + t4 * 2;
            float b0 = bias ? bias[col] : 0.f;
            float b1 = bias ? bias[col + 1] : 0.f;
            C[(size_t)row0 * N + col]           = acc[mf][nf][0] + b0;
            C[(size_t)row0 * N + col + 1]       = acc[mf][nf][1] + b1;
            C[(size_t)(row0 + 8) * N + col]     = acc[mf][nf][2] + b0;
            C[(size_t)(row0 + 8) * N + col + 1] = acc[mf][nf][3] + b1;
        }
}

// ---------------------------------------------------------------------------
// Persistent tensor-core LSTM v7 (= v6 + shuffle transpose + per-warp release).
// 128 CTAs = 64 j-groups x 2 batch halves; M=32, N=64 gate cols, K=1024.
//  - h double-buffered: read buf t&1, write buf (t+1)&1.
//  - one counter per (t,bh); target 512 (64 CTAs x 8 warps). Only warp 0
//    acquire-polls, loop-top bar.sync broadcasts AND serves as the A_s
//    reuse barrier (each warp reaches it after its own mma reads).
//  - producer arrival: per-warp — h-store, __syncwarp, lane0 red.release
//    (warp-sync is a synchronizing op -> valid release chain).
//  - gate transpose done with 4-round Latin-square shfl.idx (8 shuffles),
//    no SMEM staging, no block barriers between mma and gates.
// ---------------------------------------------------------------------------
constexpr int U_BYTES   = 1024 * 72 * 2;   // 147456
constexpr int A_BYTES   = 32 * 1032 * 2;   // 66048
constexpr int LSTM_SMEM = U_BYTES + A_BYTES;  // 213504

__global__ void __launch_bounds__(256) lstm_layer_tc7(
    const __half* __restrict__ U16,   // (1024, 4096) fp16
    const float* __restrict__ xw,     // (B*T, 4096) fp32, rows b*T+t
    const float* __restrict__ cseed,  // (B,1024) fp32 initial cell
    float* __restrict__ cout,         // (B,1024) fp32 final cell
    __half* __restrict__ h16,         // [2][B][1024] fp16 (buf0 pre-seeded)
    __half* __restrict__ ys16,        // (B*T, 1024) fp16 out
    int* __restrict__ cnt)            // [T][2] arrival counters (zeroed)
{
    extern __shared__ char sm[];
    __half* U_s = (__half*)sm;                 // [1024][72]
    __half* A_s = (__half*)(sm + U_BYTES);     // [32][1032]
    const uint32_t U_u = smem_u32(U_s);
    const uint32_t A_u = smem_u32(A_s);

    const int tid = threadIdx.x;
    const int w = tid >> 5, lane = tid & 31;
    const int jg = blockIdx.x >> 1;            // 0..63
    const int bh = blockIdx.x & 1;             // batch half
    const int j0 = jg * 16;

    // ---- preload U slice: U_s[k][w*8 + 2*gate + jj] = U16[k][gate*H + j0 + 2w + jj]
    for (int i = 0; i < 128; i++) {
        int idx = tid + i * 256;
        int k = idx >> 5;
        int gate = (idx >> 3) & 3;
        int ww = idx & 7;
        *reinterpret_cast<__half2*>(U_s + k * 72 + ww * 8 + 2 * gate) =
            *reinterpret_cast<const __half2*>(U16 + (size_t)k * G4 + gate * H_ + j0 + 2 * ww);
    }
    __syncthreads();

    const int bloc = bh * 32 + lane;
    float2 creg = *reinterpret_cast<const float2*>(cseed + (size_t)bloc * H_ + j0 + 2 * w);

    for (int t = 0; t < T_; t++) {
        // prefetch xw for this lane's two cells (independent of h)
        float2 xg[4];
        {
            size_t xbase = ((size_t)bloc * T_ + t) * (size_t)G4 + j0 + 2 * w;
#pragma unroll
            for (int gg = 0; gg < 4; gg++)
                xg[gg] = __ldg(reinterpret_cast<const float2*>(xw + xbase + (size_t)gg * H_));
        }

        // wait for h[t-1] producers (512 warp-arrivals): warp 0 polls,
        // bar.sync broadcasts AND protects A_s reuse.
        if (t > 0) {
            if (w == 0) {
                const int* cp = &cnt[(t - 1) * 2 + bh];
                while ((unsigned)ld_acquire_gpu(cp) < 512u) { }
            }
            __syncthreads();
        }

        const __half* hg = h16 + (size_t)(t & 1) * BH + (size_t)bh * 32 * H_;

        // issue all 4 h-staging chunks (256 cols each)
#pragma unroll
        for (int cch = 0; cch < 4; cch++) {
#pragma unroll
            for (int e = 0; e < 4; e++) {
                int idx = tid + e * 256;
                int r = idx >> 5, ch = idx & 31;
                cp_async16(A_u + (r * 1032 + cch * 256 + ch * 8) * 2,
                           hg + (size_t)r * H_ + cch * 256 + ch * 8);
            }
            cp_commit();
        }

        float acc0[4], acc1[4];
#pragma unroll
        for (int e = 0; e < 4; e++) { acc0[e] = 0.f; acc1[e] = 0.f; }

#define LSTM_MMA_CHUNK(C, WAITN)                                                   \
        {                                                                          \
            cp_wait_n<WAITN>();                                                    \
            __syncthreads();                                                       \
            _Pragma("unroll")                                                      \
            for (int ks2 = 0; ks2 < 8; ks2++) {                                    \
                int kk = (C) * 256 + ks2 * 32;                                     \
                uint32_t bq[4];                                                    \
                ldmatrix_x4t(bq, U_u + ((kk + lane) * 72 + w * 8) * 2);            \
                uint32_t a0[4], a1[4];                                             \
                ldmatrix_x4(a0, A_u + (((lane & 15)) * 1032                        \
                                       + kk + (lane >> 4) * 8) * 2);               \
                ldmatrix_x4(a1, A_u + ((16 + (lane & 15)) * 1032                   \
                                       + kk + (lane >> 4) * 8) * 2);               \
                mma16816(acc0, a0, bq);                                            \
                mma16816(acc1, a1, bq);                                            \
                uint32_t a2[4], a3[4];                                             \
                ldmatrix_x4(a2, A_u + (((lane & 15)) * 1032                        \
                                       + kk + 16 + (lane >> 4) * 8) * 2);          \
                ldmatrix_x4(a3, A_u + ((16 + (lane & 15)) * 1032                   \
                                       + kk + 16 + (lane >> 4) * 8) * 2);          \
                mma16816(acc0, a2, bq + 2);                                        \
                mma16816(acc1, a3, bq + 2);                                        \
            }                                                                      \
        }
        LSTM_MMA_CHUNK(0, 3)
        LSTM_MMA_CHUNK(1, 2)
        LSTM_MMA_CHUNK(2, 1)
        LSTM_MMA_CHUNK(3, 0)
#undef LSTM_MMA_CHUNK

        // ---- warp-local gate transpose via 4-round Latin-square shuffles.
        // V(row, c) lives at lane (row&7)*4 + (c>>1), part row>>3,
        // sub c&1. In round k, source lane (t4=lane&3) publishes part
        // (t4+k)&3; target (row=lane, part P=lane>>3) reads from
        // t4s=(P-k)&3 getting cols 2*t4s, 2*t4s+1.
        float vals[8];
        {
            const int P = lane >> 3;
            const int base = (lane & 7) * 4;
            const int myt4 = lane & 3;
#pragma unroll
            for (int k = 0; k < 4; k++) {
                int pp = (myt4 + k) & 3;
                float p0 = (pp == 0) ? acc0[0] : (pp == 1) ? acc0[2]
                         : (pp == 2) ? acc1[0] : acc1[2];
                float p1 = (pp == 0) ? acc0[1] : (pp == 1) ? acc0[3]
                         : (pp == 2) ? acc1[1] : acc1[3];
                int t4s = (P - k) & 3;
                int src = base + t4s;
                vals[2 * t4s]     = __shfl_sync(0xffffffffu, p0, src);
                vals[2 * t4s + 1] = __shfl_sync(0xffffffffu, p1, src);
            }
        }

        // cell update: lane handles row=lane (bloc), both j — fast-math gates
        {
            float iva = vals[0] + xg[0].x;
            float ivb = vals[1] + xg[0].y;
            float fva = vals[2] + xg[1].x;
            float fvb = vals[3] + xg[1].y;
            float gva = vals[4] + xg[2].x;
            float gvb = vals[5] + xg[2].y;
            float ova = vals[6] + xg[3].x;
            float ovb = vals[7] + xg[3].y;

            float cna = fast_sigmoid(fva) * creg.x + fast_sigmoid(iva) * fast_tanh(gva);
            float cnb = fast_sigmoid(fvb) * creg.y + fast_sigmoid(ivb) * fast_tanh(gvb);
            float hna = fast_sigmoid(ova) * fast_tanh(cna);
            float hnb = fast_sigmoid(ovb) * fast_tanh(cnb);
            creg.x = cna; creg.y = cnb;

            __half2 h2 = __floats2half2_rn(hna, hnb);
            *reinterpret_cast<__half2*>(
                h16 + (size_t)((t + 1) & 1) * BH + (size_t)bloc * H_ + j0 + 2 * w) = h2;
            *reinterpret_cast<__half2*>(
                ys16 + ((size_t)bloc * T_ + t) * (size_t)H_ + j0 + 2 * w) = h2;
        }

        // per-warp arrival: syncwarp orders the warp's h-stores before
        // lane0's release-add (counter target: 512 per (t,bh))
        __syncwarp();
        if (lane == 0) red_release_add(&cnt[t * 2 + bh], 1);
    }

    // write back final cell state
    *reinterpret_cast<float2*>(cout + (size_t)bloc * H_ + j0 + 2 * w) = creg;
}

// ---------------------------------------------------------------------------
// fc2 split-K: z2(64,36) += z1(64,131072) @ W(131072,36); z2 pre-seeded w/ bias
// ---------------------------------------------------------------------------
constexpr int FC2_SMEM = 256 * 65 * 4 + 256 * 37 * 4;  // 104448

__global__ void __launch_bounds__(256) fc2_split(
    const float* __restrict__ z1, const float* __restrict__ W,
    float* __restrict__ z2)
{
    extern __shared__ float smf[];
    float* As = smf;                 // [256 k][65 m-pad]
    float* Ws = smf + 256 * 65;      // [256 k][37 n-pad]
    const int k0 = blockIdx.x * 256;
    const int tid = threadIdx.x;

    for (int i = 0; i < 16; i++) {
        int idx = tid + i * 256;
        int m = idx >> 6, kc = (idx & 63) * 4;
        float4 v = *reinterpret_cast<const float4*>(z1 + (size_t)m * 131072 + k0 + kc);
        As[(kc + 0) * 65 + m] = v.x;
        As[(kc + 1) * 65 + m] = v.y;
        As[(kc + 2) * 65 + m] = v.z;
        As[(kc + 3) * 65 + m] = v.w;
    }
    for (int i = 0; i < 36; i++) {
        int idx = tid + i * 256;
        int k = idx / 36, n = idx - k * 36;
        Ws[k * 37 + n] = W[(size_t)(k0 + k) * 36 + n];
    }
    __syncthreads();

    const int m = tid & 63, ng = tid >> 6;
    const int n0 = ng * 9;
    float acc[9];
#pragma unroll
    for (int j = 0; j < 9; j++) acc[j] = 0.f;

    for (int k = 0; k < 256; k++) {
        float a = As[k * 65 + m];
#pragma unroll
        for (int j = 0; j < 9; j++) acc[j] = fmaf(a, Ws[k * 37 + n0 + j], acc[j]);
    }
#pragma unroll
    for (int j = 0; j < 9; j++) atomicAdd(&z2[m * 36 + n0 + j], acc[j]);
}

__global__ void z2_init(const float* __restrict__ bias, float* __restrict__ z2)
{
    int i = blockIdx.x * 256 + threadIdx.x;
    if (i < B_ * 36) z2[i] = bias[i % 36];
}

// fc3 (36->6) + fc4 (6->6) + relu
__global__ void fc34_kernel(const float* __restrict__ z2,
                            const float* __restrict__ w3, const float* __restrict__ b3,
                            const float* __restrict__ w4, const float* __restrict__ b4,
                            float* __restrict__ out)
{
    int m = threadIdx.x;
    if (m >= B_) return;
    float t3[6];
#pragma unroll
    for (int n = 0; n < 6; n++) {
        float s = b3[n];
        for (int k = 0; k < 36; k++) s = fmaf(z2[m * 36 + k], w3[k * 6 + n], s);
        t3[n] = s;
    }
#pragma unroll
    for (int n = 0; n < 6; n++) {
        float s = b4[n];
#pragma unroll
        for (int k = 0; k < 6; k++) s = fmaf(t3[k], w4[k * 6 + n], s);
        out[m * 6 + n] = fmaxf(s, 0.f);
    }
}

// ---------------------------------------------------------------------------
extern "C" void kernel_launch(void* const* d_in, const int* in_sizes, int n_in,
                              void* d_out, int out_size)
{
    const float* x     = (const float*)d_in[0];
    const float* h0    = (const float*)d_in[1];
    const float* c0    = (const float*)d_in[2];
    const float* W1    = (const float*)d_in[3];
    const float* U1    = (const float*)d_in[4];
    const float* b1    = (const float*)d_in[5];
    const float* W2    = (const float*)d_in[6];
    const float* U2    = (const float*)d_in[7];
    const float* b2    = (const float*)d_in[8];
    const float* fc1_w = (const float*)d_in[9];
    const float* fc1_b = (const float*)d_in[10];
    const float* fc2_w = (const float*)d_in[11];
    const float* fc2_b = (const float*)d_in[12];
    const float* fc3_w = (const float*)d_in[13];
    const float* fc3_b = (const float*)d_in[14];
    const float* fc4_w = (const float*)d_in[15];
    const float* fc4_b = (const float*)d_in[16];
    float* out = (float*)d_out;

    float *xw, *c, *z1, *z2;
    int* cnt;
    __half *h16, *x16, *W1_16, *U1_16, *W2_16, *U2_16, *fc1w16, *ys1_16, *ys2_16;
    cudaGetSymbolAddress((void**)&xw, g_xw);
    cudaGetSymbolAddress((void**)&c, g_c);
    cudaGetSymbolAddress((void**)&h16, g_h16);
    cudaGetSymbolAddress((void**)&x16, g_x16);
    cudaGetSymbolAddress((void**)&W1_16, g_W1_16);
    cudaGetSymbolAddress((void**)&U1_16, g_U1_16);
    cudaGetSymbolAddress((void**)&W2_16, g_W2_16);
    cudaGetSymbolAddress((void**)&U2_16, g_U2_16);
    cudaGetSymbolAddress((void**)&fc1w16, g_fc1w16);
    cudaGetSymbolAddress((void**)&ys1_16, g_ys1_16);
    cudaGetSymbolAddress((void**)&ys2_16, g_ys2_16);
    cudaGetSymbolAddress((void**)&z1, g_z1);
    cudaGetSymbolAddress((void**)&z2, g_z2);
    cudaGetSymbolAddress((void**)&cnt, g_cnt);

    static bool attr_done = false;
    if (!attr_done) {
        cudaFuncSetAttribute(lstm_layer_tc7,
                             cudaFuncAttributeMaxDynamicSharedMemorySize, LSTM_SMEM);
        cudaFuncSetAttribute(fc2_split,
                             cudaFuncAttributeMaxDynamicSharedMemorySize, FC2_SMEM);
        attr_done = true;
    }

    const int MT = B_ * T_;  // 16384

    auto conv = [](const float* src, __half* dst, int n) {
        f32_to_f16<<<(n / 4 + 255) / 256, 256>>>(src, dst, n);
    };

    conv(x, x16, MT * D_);
    conv(W1, W1_16, D_ * G4);
    hgemm<<<dim3(G4 / 128, MT / 128), 256>>>(x16, W1_16, b1, xw, MT, G4, D_);
    conv(U1, U1_16, H_ * G4);
    init_all<<<BH / 256, 256>>>(h0, h16, cnt);
    lstm_layer_tc7<<<128, 256, LSTM_SMEM>>>(U1_16, xw, c0, c, h16, ys1_16, cnt);

    conv(W2, W2_16, H_ * G4);
    conv(U2, U2_16, H_ * G4);
    conv(fc1_w, fc1w16, H_ * (H_ / 2));

    // xw = ys1 @ W2 + b2
    hgemm<<<dim3(G4 / 128, MT / 128), 256>>>(ys1_16, W2_16, b2, xw, MT, G4, H_);

    // LSTM layer 2 (h16 buf0 / c carry over — matches reference seeding)
    lstm_layer_tc7<<<128, 256, LSTM_SMEM>>>(U2_16, xw, c, c, h16, ys2_16,
                                            cnt + T_ * 2);

    // z1 = ys2 @ fc1_w + fc1_b
    hgemm<<<dim3((H_ / 2) / 128, MT / 128), 256>>>(ys2_16, fc1w16, fc1_b, z1,
                                                   MT, H_ / 2, H_);

    // fc2: z2 = bias, then split-K accumulate
    z2_init<<<(B_ * 36 + 255) / 256, 256>>>(fc2_b, z2);
    fc2_split<<<512, 256, FC2_SMEM>>>(z1, fc2_w, z2);

    // fc3 + fc4 + relu -> out (64, 6)
    fc34_kernel<<<1, 64>>>(z2, fc3_w, fc3_b, fc4_w, fc4_b, out);
}

// round 13
// speedup vs baseline: 1.0669x; 1.0669x over previous
#include <cuda_runtime.h>
#include <cuda_fp16.h>
#include <math.h>
#include <stdint.h>

// Problem constants
constexpr int B_ = 64;
constexpr int T_ = 256;
constexpr int D_ = 512;
constexpr int H_ = 1024;
constexpr int G4 = 4 * H_;         // 4096
constexpr int BH = B_ * H_;        // 65536

// ------------------------- device scratch (no allocs) ----------------------
__device__ float  g_xw[(size_t)B_ * T_ * G4];        // (B*T, 4H) fp32
__device__ float  g_c[BH];                           // cell state fp32
__device__ __half g_h16[2 * BH];                     // double-buffered hidden
__device__ __half g_x16[(size_t)B_ * T_ * D_];
__device__ __half g_W1_16[(size_t)D_ * G4];
__device__ __half g_U1_16[(size_t)H_ * G4];
__device__ __half g_W2_16[(size_t)H_ * G4];
__device__ __half g_U2_16[(size_t)H_ * G4];
__device__ __half g_fc1w16[(size_t)H_ * (H_ / 2)];
__device__ __half g_ys1_16[(size_t)B_ * T_ * H_];
__device__ __half g_ys2_16[(size_t)B_ * T_ * H_];
__device__ float  g_z1[(size_t)B_ * T_ * (H_ / 2)];
__device__ float  g_z2[B_ * 36];
__device__ int    g_cnt[2 * T_ * 2];                 // [layer][t][bh] arrivals

// ------------------------------ PTX helpers --------------------------------
__device__ __forceinline__ uint32_t smem_u32(const void* p) {
    uint32_t a;
    asm("{ .reg .u64 t; cvta.to.shared.u64 t, %1; cvt.u32.u64 %0, t; }"
        : "=r"(a) : "l"(p));
    return a;
}
__device__ __forceinline__ void cp_async16(uint32_t dst, const void* src) {
    asm volatile("cp.async.cg.shared.global [%0], [%1], 16;" :: "r"(dst), "l"(src));
}
__device__ __forceinline__ void cp_commit() {
    asm volatile("cp.async.commit_group;");
}
template <int N> __device__ __forceinline__ void cp_wait_n() {
    asm volatile("cp.async.wait_group %0;" :: "n"(N));
}
__device__ __forceinline__ void ldmatrix_x4(uint32_t* r, uint32_t addr) {
    asm volatile("ldmatrix.sync.aligned.m8n8.x4.shared.b16 {%0,%1,%2,%3}, [%4];"
                 : "=r"(r[0]), "=r"(r[1]), "=r"(r[2]), "=r"(r[3]) : "r"(addr));
}
__device__ __forceinline__ void ldmatrix_x4t(uint32_t* r, uint32_t addr) {
    asm volatile("ldmatrix.sync.aligned.m8n8.x4.trans.shared.b16 {%0,%1,%2,%3}, [%4];"
                 : "=r"(r[0]), "=r"(r[1]), "=r"(r[2]), "=r"(r[3]) : "r"(addr));
}
__device__ __forceinline__ void ldmatrix_x2t(uint32_t* r, uint32_t addr) {
    asm volatile("ldmatrix.sync.aligned.m8n8.x2.trans.shared.b16 {%0,%1}, [%2];"
                 : "=r"(r[0]), "=r"(r[1]) : "r"(addr));
}
__device__ __forceinline__ void mma16816(float* d, const uint32_t* a, const uint32_t* b) {
    asm volatile(
        "mma.sync.aligned.m16n8k16.row.col.f32.f16.f16.f32 "
        "{%0,%1,%2,%3},{%4,%5,%6,%7},{%8,%9},{%0,%1,%2,%3};"
        : "+f"(d[0]), "+f"(d[1]), "+f"(d[2]), "+f"(d[3])
        : "r"(a[0]), "r"(a[1]), "r"(a[2]), "r"(a[3]), "r"(b[0]), "r"(b[1]));
}
// acquire load (volatile asm — cannot be hoisted or deleted)
__device__ __forceinline__ int ld_acquire_gpu(const int* p) {
    int v;
    asm volatile("ld.acquire.gpu.global.s32 %0, [%1];" : "=r"(v) : "l"(p) : "memory");
    return v;
}
// release reduction
__device__ __forceinline__ void red_release_add(int* p, int v) {
    asm volatile("red.release.gpu.global.add.s32 [%0], %1;" :: "l"(p), "r"(v) : "memory");
}

// fast gate math: MUFU-based, rel err ~2e-7 (invisible vs fp16 5.6e-4)
__device__ __forceinline__ float fast_sigmoid(float x) {
    return __fdividef(1.f, 1.f + __expf(-x));
}
__device__ __forceinline__ float fast_tanh(float x) {
    return 1.f - __fdividef(2.f, __expf(2.f * x) + 1.f);
}

// ---------------------------------------------------------------------------
__global__ void f32_to_f16(const float* __restrict__ in, __half* __restrict__ out, int n)
{
    int i4 = (blockIdx.x * 256 + threadIdx.x) * 4;
    if (i4 < n) {
        float4 v = *reinterpret_cast<const float4*>(in + i4);
        *reinterpret_cast<__half2*>(out + i4)     = __floats2half2_rn(v.x, v.y);
        *reinterpret_cast<__half2*>(out + i4 + 2) = __floats2half2_rn(v.z, v.w);
    }
}

// seed h16 buf0 from h0, zero BOTH layers' arrival counters
__global__ void init_all(const float* __restrict__ h0, __half* __restrict__ h16,
                         int* __restrict__ cnt)
{
    int i = blockIdx.x * 256 + threadIdx.x;
    if (i < BH) h16[i] = __float2half_rn(h0[i]);
    if (i < 2 * T_ * 2) cnt[i] = 0;
}

// ---------------------------------------------------------------------------
// HGEMM: C_fp32(M,N) = A_fp16(M,K) @ B_fp16(K,N) + bias(N)
// 128x128x32 tile, 256 threads, THREE-stage cp.async pipeline.
// ---------------------------------------------------------------------------
__global__ void __launch_bounds__(256) hgemm(
    const __half* __restrict__ A, const __half* __restrict__ Bm,
    const float* __restrict__ bias, float* __restrict__ C,
    int M, int N, int K)
{
    __shared__ __half As[3][128 * 40];
    __shared__ __half Bs[3][32 * 136];

    const int tid = threadIdx.x;
    const int w = tid >> 5, lane = tid & 31;
    const int bm = blockIdx.y * 128, bn = blockIdx.x * 128;
    const int wm = (w >> 2) * 64, wn = (w & 3) * 32;
    const uint32_t AsU = smem_u32(As), BsU = smem_u32(Bs);

    float acc[4][4][4];
#pragma unroll
    for (int i = 0; i < 4; i++)
#pragma unroll
        for (int j = 0; j < 4; j++)
#pragma unroll
            for (int e = 0; e < 4; e++) acc[i][j][e] = 0.f;

    const int nk = K / 32;

#define LOAD_TILE(kt, buf)                                                        \
    {                                                                             \
        int k0 = (kt) * 32;                                                       \
        _Pragma("unroll")                                                         \
        for (int e = 0; e < 2; e++) {                                             \
            int idx = tid + e * 256;                                              \
            int r = idx >> 2, ch = idx & 3;                                       \
            cp_async16(AsU + ((buf) * 5120 + r * 40 + ch * 8) * 2,                \
                       A + (size_t)(bm + r) * K + k0 + ch * 8);                   \
        }                                                                         \
        _Pragma("unroll")                                                         \
        for (int e = 0; e < 2; e++) {                                             \
            int idx = tid + e * 256;                                              \
            int r = idx >> 4, ch = idx & 15;                                      \
            cp_async16(BsU + ((buf) * 4352 + r * 136 + ch * 8) * 2,               \
                       Bm + (size_t)(k0 + r) * N + bn + ch * 8);                  \
        }                                                                         \
        cp_commit();                                                              \
    }

    LOAD_TILE(0, 0)
    if (nk > 1) LOAD_TILE(1, 1)

    for (int kt = 0; kt < nk; kt++) {
        int buf = kt % 3;
        if (kt + 1 < nk) cp_wait_n<1>(); else cp_wait_n<0>();
        __syncthreads();
        if (kt + 2 < nk) LOAD_TILE(kt + 2, (kt + 2) % 3)

#pragma unroll
        for (int ks = 0; ks < 2; ks++) {
            uint32_t bfr[4][2];
#pragma unroll
            for (int nf = 0; nf < 4; nf++)
                ldmatrix_x2t(bfr[nf],
                    BsU + (buf * 4352 + (ks * 16 + (lane & 15)) * 136 + wn + nf * 8) * 2);
#pragma unroll
            for (int mf = 0; mf < 4; mf++) {
                uint32_t afr[4];
                ldmatrix_x4(afr,
                    AsU + (buf * 5120 + (wm + mf * 16 + (lane & 15)) * 40
                           + ks * 16 + ((lane >> 4) * 8)) * 2);
#pragma unroll
                for (int nf = 0; nf < 4; nf++) mma16816(acc[mf][nf], afr, bfr[nf]);
            }
        }
        __syncthreads();
    }
#undef LOAD_TILE

    const int g = lane >> 2, t4 = lane & 3;
#pragma unroll
    for (int mf = 0; mf < 4; mf++)
#pragma unroll
        for (int nf = 0; nf < 4; nf++) {
            int row0 = bm + wm + mf * 16 + g;
            int col = bn + wn + nf * 8 + t4 * 2;
            float b0 = bias ? bias[col] : 0.f;
            float b1 = bias ? bias[col + 1] : 0.f;
            C[(size_t)row0 * N + col]           = acc[mf][nf][0] + b0;
            C[(size_t)row0 * N + col + 1]       = acc[mf][nf][1] + b1;
            C[(size_t)(row0 + 8) * N + col]     = acc[mf][nf][2] + b0;
            C[(size_t)(row0 + 8) * N + col + 1] = acc[mf][nf][3] + b1;
        }
}

// ---------------------------------------------------------------------------
// Persistent tensor-core LSTM v8 = R11 structure + shuffle gate transpose,
// with BLOCK-level arrival (64 per counter — R12 showed 512 warp-arrivals
// serialize on the L2 atomic unit).
// 128 CTAs = 64 j-groups x 2 batch halves; M=32, N=64 gate cols, K=1024.
//  - h double-buffered: read buf t&1, write buf (t+1)&1.
//  - one counter per (t,bh); only warp 0 acquire-polls, loop-top bar.sync
//    broadcasts readiness.
//  - producer arrival: post-gates bar.sync (orders all threads' h-stores
//    AND all warps' A_s mma reads) then tid0 red.release.
//  - gate transpose: 4-round Latin-square shfl.idx (8 shuffles), no SMEM.
//  - WAR-safe: observing cnt[t-1]==64 implies all same-bh CTAs completed
//    their step-(t-1) staging reads of the buffer overwritten at step t.
// ---------------------------------------------------------------------------
constexpr int U_BYTES   = 1024 * 72 * 2;   // 147456
constexpr int A_BYTES   = 32 * 1032 * 2;   // 66048
constexpr int LSTM_SMEM = U_BYTES + A_BYTES;  // 213504

__global__ void __launch_bounds__(256) lstm_layer_tc8(
    const __half* __restrict__ U16,   // (1024, 4096) fp16
    const float* __restrict__ xw,     // (B*T, 4096) fp32, rows b*T+t
    const float* __restrict__ cseed,  // (B,1024) fp32 initial cell
    float* __restrict__ cout,         // (B,1024) fp32 final cell
    __half* __restrict__ h16,         // [2][B][1024] fp16 (buf0 pre-seeded)
    __half* __restrict__ ys16,        // (B*T, 1024) fp16 out
    int* __restrict__ cnt)            // [T][2] arrival counters (zeroed)
{
    extern __shared__ char sm[];
    __half* U_s = (__half*)sm;                 // [1024][72]
    __half* A_s = (__half*)(sm + U_BYTES);     // [32][1032]
    const uint32_t U_u = smem_u32(U_s);
    const uint32_t A_u = smem_u32(A_s);

    const int tid = threadIdx.x;
    const int w = tid >> 5, lane = tid & 31;
    const int jg = blockIdx.x >> 1;            // 0..63
    const int bh = blockIdx.x & 1;             // batch half
    const int j0 = jg * 16;

    // ---- preload U slice: U_s[k][w*8 + 2*gate + jj] = U16[k][gate*H + j0 + 2w + jj]
    for (int i = 0; i < 128; i++) {
        int idx = tid + i * 256;
        int k = idx >> 5;
        int gate = (idx >> 3) & 3;
        int ww = idx & 7;
        *reinterpret_cast<__half2*>(U_s + k * 72 + ww * 8 + 2 * gate) =
            *reinterpret_cast<const __half2*>(U16 + (size_t)k * G4 + gate * H_ + j0 + 2 * ww);
    }
    __syncthreads();

    const int bloc = bh * 32 + lane;
    float2 creg = *reinterpret_cast<const float2*>(cseed + (size_t)bloc * H_ + j0 + 2 * w);

    for (int t = 0; t < T_; t++) {
        // prefetch xw for this lane's two cells (independent of h)
        float2 xg[4];
        {
            size_t xbase = ((size_t)bloc * T_ + t) * (size_t)G4 + j0 + 2 * w;
#pragma unroll
            for (int gg = 0; gg < 4; gg++)
                xg[gg] = __ldg(reinterpret_cast<const float2*>(xw + xbase + (size_t)gg * H_));
        }

        // wait for h[t-1] producers (64 CTA-arrivals): warp 0 polls, bar broadcasts
        if (t > 0) {
            if (w == 0) {
                const int* cp = &cnt[(t - 1) * 2 + bh];
                while ((unsigned)ld_acquire_gpu(cp) < 64u) { }
            }
            __syncthreads();
        }

        const __half* hg = h16 + (size_t)(t & 1) * BH + (size_t)bh * 32 * H_;

        // issue all 4 h-staging chunks (256 cols each)
#pragma unroll
        for (int cch = 0; cch < 4; cch++) {
#pragma unroll
            for (int e = 0; e < 4; e++) {
                int idx = tid + e * 256;
                int r = idx >> 5, ch = idx & 31;
                cp_async16(A_u + (r * 1032 + cch * 256 + ch * 8) * 2,
                           hg + (size_t)r * H_ + cch * 256 + ch * 8);
            }
            cp_commit();
        }

        float acc0[4], acc1[4];
#pragma unroll
        for (int e = 0; e < 4; e++) { acc0[e] = 0.f; acc1[e] = 0.f; }

#define LSTM_MMA_CHUNK(C, WAITN)                                                   \
        {                                                                          \
            cp_wait_n<WAITN>();                                                    \
            __syncthreads();                                                       \
            _Pragma("unroll")                                                      \
            for (int ks2 = 0; ks2 < 8; ks2++) {                                    \
                int kk = (C) * 256 + ks2 * 32;                                     \
                uint32_t bq[4];                                                    \
                ldmatrix_x4t(bq, U_u + ((kk + lane) * 72 + w * 8) * 2);            \
                uint32_t a0[4], a1[4];                                             \
                ldmatrix_x4(a0, A_u + (((lane & 15)) * 1032                        \
                                       + kk + (lane >> 4) * 8) * 2);               \
                ldmatrix_x4(a1, A_u + ((16 + (lane & 15)) * 1032                   \
                                       + kk + (lane >> 4) * 8) * 2);               \
                mma16816(acc0, a0, bq);                                            \
                mma16816(acc1, a1, bq);                                            \
                uint32_t a2[4], a3[4];                                             \
                ldmatrix_x4(a2, A_u + (((lane & 15)) * 1032                        \
                                       + kk + 16 + (lane >> 4) * 8) * 2);          \
                ldmatrix_x4(a3, A_u + ((16 + (lane & 15)) * 1032                   \
                                       + kk + 16 + (lane >> 4) * 8) * 2);          \
                mma16816(acc0, a2, bq + 2);                                        \
                mma16816(acc1, a3, bq + 2);                                        \
            }                                                                      \
        }
        LSTM_MMA_CHUNK(0, 3)
        LSTM_MMA_CHUNK(1, 2)
        LSTM_MMA_CHUNK(2, 1)
        LSTM_MMA_CHUNK(3, 0)
#undef LSTM_MMA_CHUNK

        // ---- warp-local gate transpose via 4-round Latin-square shuffles.
        // V(row, c) lives at lane (row&7)*4 + (c>>1), part row>>3, sub c&1.
        // Round k: source lane (t4) publishes part (t4+k)&3; target
        // (row=lane, part P=lane>>3) reads from t4s=(P-k)&3, cols 2*t4s(+1).
        float vals[8];
        {
            const int P = lane >> 3;
            const int base = (lane & 7) * 4;
            const int myt4 = lane & 3;
#pragma unroll
            for (int k = 0; k < 4; k++) {
                int pp = (myt4 + k) & 3;
                float p0 = (pp == 0) ? acc0[0] : (pp == 1) ? acc0[2]
                         : (pp == 2) ? acc1[0] : acc1[2];
                float p1 = (pp == 0) ? acc0[1] : (pp == 1) ? acc0[3]
                         : (pp == 2) ? acc1[1] : acc1[3];
                int t4s = (P - k) & 3;
                int src = base + t4s;
                vals[2 * t4s]     = __shfl_sync(0xffffffffu, p0, src);
                vals[2 * t4s + 1] = __shfl_sync(0xffffffffu, p1, src);
            }
        }

        // cell update: lane handles row=lane (bloc), both j — fast-math gates
        {
            float iva = vals[0] + xg[0].x;
            float ivb = vals[1] + xg[0].y;
            float fva = vals[2] + xg[1].x;
            float fvb = vals[3] + xg[1].y;
            float gva = vals[4] + xg[2].x;
            float gvb = vals[5] + xg[2].y;
            float ova = vals[6] + xg[3].x;
            float ovb = vals[7] + xg[3].y;

            float cna = fast_sigmoid(fva) * creg.x + fast_sigmoid(iva) * fast_tanh(gva);
            float cnb = fast_sigmoid(fvb) * creg.y + fast_sigmoid(ivb) * fast_tanh(gvb);
            float hna = fast_sigmoid(ova) * fast_tanh(cna);
            float hnb = fast_sigmoid(ovb) * fast_tanh(cnb);
            creg.x = cna; creg.y = cnb;

            __half2 h2 = __floats2half2_rn(hna, hnb);
            *reinterpret_cast<__half2*>(
                h16 + (size_t)((t + 1) & 1) * BH + (size_t)bloc * H_ + j0 + 2 * w) = h2;
            *reinterpret_cast<__half2*>(
                ys16 + ((size_t)bloc * T_ + t) * (size_t)H_ + j0 + 2 * w) = h2;
        }

        // arrive: bar.sync orders all threads' h-stores (and A_s reads)
        // before tid0's single release-add (counter target: 64 per (t,bh))
        __syncthreads();
        if (tid == 0) red_release_add(&cnt[t * 2 + bh], 1);
    }

    // write back final cell state
    *reinterpret_cast<float2*>(cout + (size_t)bloc * H_ + j0 + 2 * w) = creg;
}

// ---------------------------------------------------------------------------
// fc2 split-K: z2(64,36) += z1(64,131072) @ W(131072,36); z2 pre-seeded w/ bias
// ---------------------------------------------------------------------------
constexpr int FC2_SMEM = 256 * 65 * 4 + 256 * 37 * 4;  // 104448

__global__ void __launch_bounds__(256) fc2_split(
    const float* __restrict__ z1, const float* __restrict__ W,
    float* __restrict__ z2)
{
    extern __shared__ float smf[];
    float* As = smf;                 // [256 k][65 m-pad]
    float* Ws = smf + 256 * 65;      // [256 k][37 n-pad]
    const int k0 = blockIdx.x * 256;
    const int tid = threadIdx.x;

    for (int i = 0; i < 16; i++) {
        int idx = tid + i * 256;
        int m = idx >> 6, kc = (idx & 63) * 4;
        float4 v = *reinterpret_cast<const float4*>(z1 + (size_t)m * 131072 + k0 + kc);
        As[(kc + 0) * 65 + m] = v.x;
        As[(kc + 1) * 65 + m] = v.y;
        As[(kc + 2) * 65 + m] = v.z;
        As[(kc + 3) * 65 + m] = v.w;
    }
    for (int i = 0; i < 36; i++) {
        int idx = tid + i * 256;
        int k = idx / 36, n = idx - k * 36;
        Ws[k * 37 + n] = W[(size_t)(k0 + k) * 36 + n];
    }
    __syncthreads();

    const int m = tid & 63, ng = tid >> 6;
    const int n0 = ng * 9;
    float acc[9];
#pragma unroll
    for (int j = 0; j < 9; j++) acc[j] = 0.f;

    for (int k = 0; k < 256; k++) {
        float a = As[k * 65 + m];
#pragma unroll
        for (int j = 0; j < 9; j++) acc[j] = fmaf(a, Ws[k * 37 + n0 + j], acc[j]);
    }
#pragma unroll
    for (int j = 0; j < 9; j++) atomicAdd(&z2[m * 36 + n0 + j], acc[j]);
}

__global__ void z2_init(const float* __restrict__ bias, float* __restrict__ z2)
{
    int i = blockIdx.x * 256 + threadIdx.x;
    if (i < B_ * 36) z2[i] = bias[i % 36];
}

// fc3 (36->6) + fc4 (6->6) + relu
__global__ void fc34_kernel(const float* __restrict__ z2,
                            const float* __restrict__ w3, const float* __restrict__ b3,
                            const float* __restrict__ w4, const float* __restrict__ b4,
                            float* __restrict__ out)
{
    int m = threadIdx.x;
    if (m >= B_) return;
    float t3[6];
#pragma unroll
    for (int n = 0; n < 6; n++) {
        float s = b3[n];
        for (int k = 0; k < 36; k++) s = fmaf(z2[m * 36 + k], w3[k * 6 + n], s);
        t3[n] = s;
    }
#pragma unroll
    for (int n = 0; n < 6; n++) {
        float s = b4[n];
#pragma unroll
        for (int k = 0; k < 6; k++) s = fmaf(t3[k], w4[k * 6 + n], s);
        out[m * 6 + n] = fmaxf(s, 0.f);
    }
}

// ---------------------------------------------------------------------------
extern "C" void kernel_launch(void* const* d_in, const int* in_sizes, int n_in,
                              void* d_out, int out_size)
{
    const float* x     = (const float*)d_in[0];
    const float* h0    = (const float*)d_in[1];
    const float* c0    = (const float*)d_in[2];
    const float* W1    = (const float*)d_in[3];
    const float* U1    = (const float*)d_in[4];
    const float* b1    = (const float*)d_in[5];
    const float* W2    = (const float*)d_in[6];
    const float* U2    = (const float*)d_in[7];
    const float* b2    = (const float*)d_in[8];
    const float* fc1_w = (const float*)d_in[9];
    const float* fc1_b = (const float*)d_in[10];
    const float* fc2_w = (const float*)d_in[11];
    const float* fc2_b = (const float*)d_in[12];
    const float* fc3_w = (const float*)d_in[13];
    const float* fc3_b = (const float*)d_in[14];
    const float* fc4_w = (const float*)d_in[15];
    const float* fc4_b = (const float*)d_in[16];
    float* out = (float*)d_out;

    float *xw, *c, *z1, *z2;
    int* cnt;
    __half *h16, *x16, *W1_16, *U1_16, *W2_16, *U2_16, *fc1w16, *ys1_16, *ys2_16;
    cudaGetSymbolAddress((void**)&xw, g_xw);
    cudaGetSymbolAddress((void**)&c, g_c);
    cudaGetSymbolAddress((void**)&h16, g_h16);
    cudaGetSymbolAddress((void**)&x16, g_x16);
    cudaGetSymbolAddress((void**)&W1_16, g_W1_16);
    cudaGetSymbolAddress((void**)&U1_16, g_U1_16);
    cudaGetSymbolAddress((void**)&W2_16, g_W2_16);
    cudaGetSymbolAddress((void**)&U2_16, g_U2_16);
    cudaGetSymbolAddress((void**)&fc1w16, g_fc1w16);
    cudaGetSymbolAddress((void**)&ys1_16, g_ys1_16);
    cudaGetSymbolAddress((void**)&ys2_16, g_ys2_16);
    cudaGetSymbolAddress((void**)&z1, g_z1);
    cudaGetSymbolAddress((void**)&z2, g_z2);
    cudaGetSymbolAddress((void**)&cnt, g_cnt);

    static bool attr_done = false;
    if (!attr_done) {
        cudaFuncSetAttribute(lstm_layer_tc8,
                             cudaFuncAttributeMaxDynamicSharedMemorySize, LSTM_SMEM);
        cudaFuncSetAttribute(fc2_split,
                             cudaFuncAttributeMaxDynamicSharedMemorySize, FC2_SMEM);
        attr_done = true;
    }

    const int MT = B_ * T_;  // 16384

    auto conv = [](const float* src, __half* dst, int n) {
        f32_to_f16<<<(n / 4 + 255) / 256, 256>>>(src, dst, n);
    };

    conv(x, x16, MT * D_);
    conv(W1, W1_16, D_ * G4);
    hgemm<<<dim3(G4 / 128, MT / 128), 256>>>(x16, W1_16, b1, xw, MT, G4, D_);
    conv(U1, U1_16, H_ * G4);
    init_all<<<BH / 256, 256>>>(h0, h16, cnt);
    lstm_layer_tc8<<<128, 256, LSTM_SMEM>>>(U1_16, xw, c0, c, h16, ys1_16, cnt);

    conv(W2, W2_16, H_ * G4);
    conv(U2, U2_16, H_ * G4);
    conv(fc1_w, fc1w16, H_ * (H_ / 2));

    // xw = ys1 @ W2 + b2
    hgemm<<<dim3(G4 / 128, MT / 128), 256>>>(ys1_16, W2_16, b2, xw, MT, G4, H_);

    // LSTM layer 2 (h16 buf0 / c carry over — matches reference seeding)
    lstm_layer_tc8<<<128, 256, LSTM_SMEM>>>(U2_16, xw, c, c, h16, ys2_16,
                                            cnt + T_ * 2);

    // z1 = ys2 @ fc1_w + fc1_b
    hgemm<<<dim3((H_ / 2) / 128, MT / 128), 256>>>(ys2_16, fc1w16, fc1_b, z1,
                                                   MT, H_ / 2, H_);

    // fc2: z2 = bias, then split-K accumulate
    z2_init<<<(B_ * 36 + 255) / 256, 256>>>(fc2_b, z2);
    fc2_split<<<512, 256, FC2_SMEM>>>(z1, fc2_w, z2);

    // fc3 + fc4 + relu -> out (64, 6)
    fc34_kernel<<<1, 64>>>(z2, fc3_w, fc3_b, fc4_w, fc4_b, out);
}

// round 14
// speedup vs baseline: 1.1478x; 1.0758x over previous
#include <cuda_runtime.h>
#include <cuda_fp16.h>
#include <math.h>
#include <stdint.h>

// Problem constants
constexpr int B_ = 64;
constexpr int T_ = 256;
constexpr int D_ = 512;
constexpr int H_ = 1024;
constexpr int G4 = 4 * H_;         // 4096
constexpr int BH = B_ * H_;        // 65536

// ------------------------- device scratch (no allocs) ----------------------
__device__ float  g_xw[(size_t)B_ * T_ * G4];        // (B*T, 4H) fp32
__device__ float  g_c[BH];                           // cell state fp32
__device__ __half g_h16[2 * BH];                     // double-buffered hidden
__device__ __half g_x16[(size_t)B_ * T_ * D_];
__device__ __half g_W1_16[(size_t)D_ * G4];
__device__ __half g_U1_16[(size_t)H_ * G4];
__device__ __half g_W2_16[(size_t)H_ * G4];
__device__ __half g_U2_16[(size_t)H_ * G4];
__device__ __half g_fc1w16[(size_t)H_ * (H_ / 2)];
__device__ __half g_ys1_16[(size_t)B_ * T_ * H_];
__device__ __half g_ys2_16[(size_t)B_ * T_ * H_];
__device__ float  g_z1[(size_t)B_ * T_ * (H_ / 2)];
__device__ float  g_z2[B_ * 36];
__device__ int    g_cnt[2 * T_ * 2];                 // [layer][t][bh] arrivals

// ------------------------------ PTX helpers --------------------------------
__device__ __forceinline__ uint32_t smem_u32(const void* p) {
    uint32_t a;
    asm("{ .reg .u64 t; cvta.to.shared.u64 t, %1; cvt.u32.u64 %0, t; }"
        : "=r"(a) : "l"(p));
    return a;
}
__device__ __forceinline__ void cp_async16(uint32_t dst, const void* src) {
    asm volatile("cp.async.cg.shared.global [%0], [%1], 16;" :: "r"(dst), "l"(src));
}
__device__ __forceinline__ void cp_commit() {
    asm volatile("cp.async.commit_group;");
}
template <int N> __device__ __forceinline__ void cp_wait_n() {
    asm volatile("cp.async.wait_group %0;" :: "n"(N));
}
__device__ __forceinline__ void ldmatrix_x4(uint32_t* r, uint32_t addr) {
    asm volatile("ldmatrix.sync.aligned.m8n8.x4.shared.b16 {%0,%1,%2,%3}, [%4];"
                 : "=r"(r[0]), "=r"(r[1]), "=r"(r[2]), "=r"(r[3]) : "r"(addr));
}
__device__ __forceinline__ void ldmatrix_x4t(uint32_t* r, uint32_t addr) {
    asm volatile("ldmatrix.sync.aligned.m8n8.x4.trans.shared.b16 {%0,%1,%2,%3}, [%4];"
                 : "=r"(r[0]), "=r"(r[1]), "=r"(r[2]), "=r"(r[3]) : "r"(addr));
}
__device__ __forceinline__ void ldmatrix_x2t(uint32_t* r, uint32_t addr) {
    asm volatile("ldmatrix.sync.aligned.m8n8.x2.trans.shared.b16 {%0,%1}, [%2];"
                 : "=r"(r[0]), "=r"(r[1]) : "r"(addr));
}
__device__ __forceinline__ void mma16816(float* d, const uint32_t* a, const uint32_t* b) {
    asm volatile(
        "mma.sync.aligned.m16n8k16.row.col.f32.f16.f16.f32 "
        "{%0,%1,%2,%3},{%4,%5,%6,%7},{%8,%9},{%0,%1,%2,%3};"
        : "+f"(d[0]), "+f"(d[1]), "+f"(d[2]), "+f"(d[3])
        : "r"(a[0]), "r"(a[1]), "r"(a[2]), "r"(a[3]), "r"(b[0]), "r"(b[1]));
}
// acquire load (volatile asm — cannot be hoisted or deleted)
__device__ __forceinline__ int ld_acquire_gpu(const int* p) {
    int v;
    asm volatile("ld.acquire.gpu.global.s32 %0, [%1];" : "=r"(v) : "l"(p) : "memory");
    return v;
}
// release reduction
__device__ __forceinline__ void red_release_add(int* p, int v) {
    asm volatile("red.release.gpu.global.add.s32 [%0], %1;" :: "l"(p), "r"(v) : "memory");
}

// fast gate math: MUFU-based, rel err ~2e-7 (invisible vs fp16 5.6e-4)
__device__ __forceinline__ float fast_sigmoid(float x) {
    return __fdividef(1.f, 1.f + __expf(-x));
}
__device__ __forceinline__ float fast_tanh(float x) {
    return 1.f - __fdividef(2.f, __expf(2.f * x) + 1.f);
}

// ---------------------------------------------------------------------------
__global__ void f32_to_f16(const float* __restrict__ in, __half* __restrict__ out, int n)
{
    int i4 = (blockIdx.x * 256 + threadIdx.x) * 4;
    if (i4 < n) {
        float4 v = *reinterpret_cast<const float4*>(in + i4);
        *reinterpret_cast<__half2*>(out + i4)     = __floats2half2_rn(v.x, v.y);
        *reinterpret_cast<__half2*>(out + i4 + 2) = __floats2half2_rn(v.z, v.w);
    }
}

// seed h16 buf0 from h0, zero BOTH layers' arrival counters
__global__ void init_all(const float* __restrict__ h0, __half* __restrict__ h16,
                         int* __restrict__ cnt)
{
    int i = blockIdx.x * 256 + threadIdx.x;
    if (i < BH) h16[i] = __float2half_rn(h0[i]);
    if (i < 2 * T_ * 2) cnt[i] = 0;
}

// ---------------------------------------------------------------------------
// HGEMM: C_fp32(M,N) = A_fp16(M,K) @ B_fp16(K,N) + bias(N)
// 128x128x32 tile, 256 threads, THREE-stage cp.async pipeline.
// ---------------------------------------------------------------------------
__global__ void __launch_bounds__(256) hgemm(
    const __half* __restrict__ A, const __half* __restrict__ Bm,
    const float* __restrict__ bias, float* __restrict__ C,
    int M, int N, int K)
{
    __shared__ __half As[3][128 * 40];
    __shared__ __half Bs[3][32 * 136];

    const int tid = threadIdx.x;
    const int w = tid >> 5, lane = tid & 31;
    const int bm = blockIdx.y * 128, bn = blockIdx.x * 128;
    const int wm = (w >> 2) * 64, wn = (w & 3) * 32;
    const uint32_t AsU = smem_u32(As), BsU = smem_u32(Bs);

    float acc[4][4][4];
#pragma unroll
    for (int i = 0; i < 4; i++)
#pragma unroll
        for (int j = 0; j < 4; j++)
#pragma unroll
            for (int e = 0; e < 4; e++) acc[i][j][e] = 0.f;

    const int nk = K / 32;

#define LOAD_TILE(kt, buf)                                                        \
    {                                                                             \
        int k0 = (kt) * 32;                                                       \
        _Pragma("unroll")                                                         \
        for (int e = 0; e < 2; e++) {                                             \
            int idx = tid + e * 256;                                              \
            int r = idx >> 2, ch = idx & 3;                                       \
            cp_async16(AsU + ((buf) * 5120 + r * 40 + ch * 8) * 2,                \
                       A + (size_t)(bm + r) * K + k0 + ch * 8);                   \
        }                                                                         \
        _Pragma("unroll")                                                         \
        for (int e = 0; e < 2; e++) {                                             \
            int idx = tid + e * 256;                                              \
            int r = idx >> 4, ch = idx & 15;                                      \
            cp_async16(BsU + ((buf) * 4352 + r * 136 + ch * 8) * 2,               \
                       Bm + (size_t)(k0 + r) * N + bn + ch * 8);                  \
        }                                                                         \
        cp_commit();                                                              \
    }

    LOAD_TILE(0, 0)
    if (nk > 1) LOAD_TILE(1, 1)

    for (int kt = 0; kt < nk; kt++) {
        int buf = kt % 3;
        if (kt + 1 < nk) cp_wait_n<1>(); else cp_wait_n<0>();
        __syncthreads();
        if (kt + 2 < nk) LOAD_TILE(kt + 2, (kt + 2) % 3)

#pragma unroll
        for (int ks = 0; ks < 2; ks++) {
            uint32_t bfr[4][2];
#pragma unroll
            for (int nf = 0; nf < 4; nf++)
                ldmatrix_x2t(bfr[nf],
                    BsU + (buf * 4352 + (ks * 16 + (lane & 15)) * 136 + wn + nf * 8) * 2);
#pragma unroll
            for (int mf = 0; mf < 4; mf++) {
                uint32_t afr[4];
                ldmatrix_x4(afr,
                    AsU + (buf * 5120 + (wm + mf * 16 + (lane & 15)) * 40
                           + ks * 16 + ((lane >> 4) * 8)) * 2);
#pragma unroll
                for (int nf = 0; nf < 4; nf++) mma16816(acc[mf][nf], afr, bfr[nf]);
            }
        }
        __syncthreads();
    }
#undef LOAD_TILE

    const int g = lane >> 2, t4 = lane & 3;
#pragma unroll
    for (int mf = 0; mf < 4; mf++)
#pragma unroll
        for (int nf = 0; nf < 4; nf++) {
            int row0 = bm + wm + mf * 16 + g;
            int col = bn + wn + nf * 8 + t4 * 2;
            float b0 = bias ? bias[col] : 0.f;
            float b1 = bias ? bias[col + 1] : 0.f;
            C[(size_t)row0 * N + col]           = acc[mf][nf][0] + b0;
            C[(size_t)row0 * N + col + 1]       = acc[mf][nf][1] + b1;
            C[(size_t)(row0 + 8) * N + col]     = acc[mf][nf][2] + b0;
            C[(size_t)(row0 + 8) * N + col + 1] = acc[mf][nf][3] + b1;
        }
}

// ---------------------------------------------------------------------------
// Persistent tensor-core LSTM v9 — SPLIT-K warps (minimum SMEM traffic).
// 128 CTAs = 64 j-groups x 2 batch halves; CTA tile M=32, N=64 gate cols,
// K=1024. Warp w owns k-slice [128w, 128w+128) and computes PARTIALS for
// all 64 gate cols; partials reduced through SMEM.
//  - per-warp h staging: warp w cp.asyncs only its own 8KB k-slice into
//    A_s (own commit group, wait 0) — NO block barrier before mma.
//  - SMEM traffic/step: 64KB stage + 64KB A-LDSM + 128KB B-LDSM +
//    64+64KB partial w/r = 384KB (was ~704KB).
//  - partials ([8][32][66] fp32) alias A_s; post-mma barrier protects WAR.
//  - epilogue: thread owns (b=tid>>3, jpair=tid&7); 8-warp float2 reduce,
//    gates, h/ys store; barrier; tid0 red.release (target 64).
//  - h double-buffered (read t&1, write (t+1)&1); warp0 acquire-polls.
// ---------------------------------------------------------------------------
constexpr int U_BYTES    = 1024 * 72 * 2;     // 147456
constexpr int PART_BYTES = 8 * 32 * 66 * 4;   // 67584 (A_s 66048 aliases inside)
constexpr int LSTM_SMEM  = U_BYTES + PART_BYTES;  // 215040

__global__ void __launch_bounds__(256) lstm_layer_tc9(
    const __half* __restrict__ U16,   // (1024, 4096) fp16
    const float* __restrict__ xw,     // (B*T, 4096) fp32, rows b*T+t
    const float* __restrict__ cseed,  // (B,1024) fp32 initial cell
    float* __restrict__ cout,         // (B,1024) fp32 final cell
    __half* __restrict__ h16,         // [2][B][1024] fp16 (buf0 pre-seeded)
    __half* __restrict__ ys16,        // (B*T, 1024) fp16 out
    int* __restrict__ cnt)            // [T][2] arrival counters (zeroed)
{
    extern __shared__ char sm[];
    __half* U_s = (__half*)sm;                 // [1024][72]
    __half* A_s = (__half*)(sm + U_BYTES);     // [32][1032] (66048 B)
    float*  part = (float*)(sm + U_BYTES);     // [8][32][66] fp32 alias
    const uint32_t U_u = smem_u32(U_s);
    const uint32_t A_u = smem_u32(A_s);

    const int tid = threadIdx.x;
    const int w = tid >> 5, lane = tid & 31;
    const int jg = blockIdx.x >> 1;            // 0..63
    const int bh = blockIdx.x & 1;             // batch half
    const int j0 = jg * 16;
    const int kb = w * 128;                    // this warp's k-slice base

    // ---- preload U slice: U_s[k][jp*8 + 2*gate + jj] = U16[k][gate*H + j0 + 2*jp + jj]
    for (int i = 0; i < 128; i++) {
        int idx = tid + i * 256;
        int k = idx >> 5;
        int gate = (idx >> 3) & 3;
        int jp = idx & 7;
        *reinterpret_cast<__half2*>(U_s + k * 72 + jp * 8 + 2 * gate) =
            *reinterpret_cast<const __half2*>(U16 + (size_t)k * G4 + gate * H_ + j0 + 2 * jp);
    }
    __syncthreads();

    // epilogue cell ownership: thread -> (local row eb, j-pair ejp), 2 cells (e=0,1)
    const int eb = tid >> 3;                   // 0..31
    const int ejp = tid & 7;                   // 0..7
    const int bloc = bh * 32 + eb;
    float2 creg = *reinterpret_cast<const float2*>(cseed + (size_t)bloc * H_ + j0 + 2 * ejp);

    for (int t = 0; t < T_; t++) {
        // prefetch xw for this thread's two cells (independent of h)
        float2 xg[4];
        {
            size_t xbase = ((size_t)bloc * T_ + t) * (size_t)G4 + j0 + 2 * ejp;
#pragma unroll
            for (int gg = 0; gg < 4; gg++)
                xg[gg] = __ldg(reinterpret_cast<const float2*>(xw + xbase + (size_t)gg * H_));
        }

        // wait for h[t-1] producers (64 CTA-arrivals): warp 0 polls, bar broadcasts
        if (t > 0) {
            if (w == 0) {
                const int* cp = &cnt[(t - 1) * 2 + bh];
                while ((unsigned)ld_acquire_gpu(cp) < 64u) { }
            }
            __syncthreads();
        }

        const __half* hg = h16 + (size_t)(t & 1) * BH + (size_t)bh * 32 * H_;

        // warp-local staging of OWN k-slice: 32 rows x 128 cols = 8KB
#pragma unroll
        for (int i = 0; i < 16; i++) {
            int idx = i * 32 + lane;
            int r = idx >> 4;          // 0..31 (two rows per i)
            int ch = idx & 15;         // 0..15 (16 x 8 halfs = 128 cols)
            cp_async16(A_u + (r * 1032 + kb + ch * 8) * 2,
                       hg + (size_t)r * H_ + kb + ch * 8);
        }
        cp_commit();
        cp_wait_n<0>();                // warp-local; no block barrier needed

        float acc[2][8][4];
#pragma unroll
        for (int mg = 0; mg < 2; mg++)
#pragma unroll
            for (int ng = 0; ng < 8; ng++)
#pragma unroll
                for (int e = 0; e < 4; e++) acc[mg][ng][e] = 0.f;

#pragma unroll
        for (int ks2 = 0; ks2 < 4; ks2++) {
            int kk = kb + ks2 * 32;
            uint32_t a0[4], a1[4], a2[4], a3[4];
            ldmatrix_x4(a0, A_u + (((lane & 15)) * 1032 + kk + (lane >> 4) * 8) * 2);
            ldmatrix_x4(a1, A_u + ((16 + (lane & 15)) * 1032 + kk + (lane >> 4) * 8) * 2);
            ldmatrix_x4(a2, A_u + (((lane & 15)) * 1032 + kk + 16 + (lane >> 4) * 8) * 2);
            ldmatrix_x4(a3, A_u + ((16 + (lane & 15)) * 1032 + kk + 16 + (lane >> 4) * 8) * 2);
#pragma unroll
            for (int ng = 0; ng < 8; ng++) {
                uint32_t bq[4];
                ldmatrix_x4t(bq, U_u + ((kk + lane) * 72 + ng * 8) * 2);
                mma16816(acc[0][ng], a0, bq);
                mma16816(acc[1][ng], a1, bq);
                mma16816(acc[0][ng], a2, bq + 2);
                mma16816(acc[1][ng], a3, bq + 2);
            }
        }
        __syncthreads();   // all warps' A_s reads done; partials may alias now

        // write partials: part[w][row][col], rows padded to 66 floats
        {
            float* pw = part + w * (32 * 66);
            const int pr = lane >> 2, pc = (lane & 3) * 2;
#pragma unroll
            for (int mg = 0; mg < 2; mg++)
#pragma unroll
                for (int ng = 0; ng < 8; ng++) {
                    int row = mg * 16 + pr;
                    *reinterpret_cast<float2*>(pw + row * 66 + ng * 8 + pc) =
                        make_float2(acc[mg][ng][0], acc[mg][ng][1]);
                    *reinterpret_cast<float2*>(pw + (row + 8) * 66 + ng * 8 + pc) =
                        make_float2(acc[mg][ng][2], acc[mg][ng][3]);
                }
        }
        __syncthreads();

        // reduce 8 warp-partials + cell update (thread: row eb, cols ejp*8+2g+e)
        {
            float2 gt[4];
#pragma unroll
            for (int gg = 0; gg < 4; gg++) {
                int c = ejp * 8 + 2 * gg;
                float2 s = make_float2(0.f, 0.f);
#pragma unroll
                for (int ww = 0; ww < 8; ww++) {
                    float2 v = *reinterpret_cast<const float2*>(
                        part + ww * (32 * 66) + eb * 66 + c);
                    s.x += v.x; s.y += v.y;
                }
                gt[gg] = s;
            }

            float iva = gt[0].x + xg[0].x;
            float ivb = gt[0].y + xg[0].y;
            float fva = gt[1].x + xg[1].x;
            float fvb = gt[1].y + xg[1].y;
            float gva = gt[2].x + xg[2].x;
            float gvb = gt[2].y + xg[2].y;
            float ova = gt[3].x + xg[3].x;
            float ovb = gt[3].y + xg[3].y;

            float cna = fast_sigmoid(fva) * creg.x + fast_sigmoid(iva) * fast_tanh(gva);
            float cnb = fast_sigmoid(fvb) * creg.y + fast_sigmoid(ivb) * fast_tanh(gvb);
            float hna = fast_sigmoid(ova) * fast_tanh(cna);
            float hnb = fast_sigmoid(ovb) * fast_tanh(cnb);
            creg.x = cna; creg.y = cnb;

            __half2 h2 = __floats2half2_rn(hna, hnb);
            *reinterpret_cast<__half2*>(
                h16 + (size_t)((t + 1) & 1) * BH + (size_t)bloc * H_ + j0 + 2 * ejp) = h2;
            *reinterpret_cast<__half2*>(
                ys16 + ((size_t)bloc * T_ + t) * (size_t)H_ + j0 + 2 * ejp) = h2;
        }

        // arrive: bar.sync orders all threads' h-stores (and partial reads)
        // before tid0's single release-add (counter target: 64 per (t,bh))
        __syncthreads();
        if (tid == 0) red_release_add(&cnt[t * 2 + bh], 1);
    }

    // write back final cell state
    *reinterpret_cast<float2*>(cout + (size_t)bloc * H_ + j0 + 2 * ejp) = creg;
}

// ---------------------------------------------------------------------------
// fc2 split-K: z2(64,36) += z1(64,131072) @ W(131072,36); z2 pre-seeded w/ bias
// ---------------------------------------------------------------------------
constexpr int FC2_SMEM = 256 * 65 * 4 + 256 * 37 * 4;  // 104448

__global__ void __launch_bounds__(256) fc2_split(
    const float* __restrict__ z1, const float* __restrict__ W,
    float* __restrict__ z2)
{
    extern __shared__ float smf[];
    float* As = smf;                 // [256 k][65 m-pad]
    float* Ws = smf + 256 * 65;      // [256 k][37 n-pad]
    const int k0 = blockIdx.x * 256;
    const int tid = threadIdx.x;

    for (int i = 0; i < 16; i++) {
        int idx = tid + i * 256;
        int m = idx >> 6, kc = (idx & 63) * 4;
        float4 v = *reinterpret_cast<const float4*>(z1 + (size_t)m * 131072 + k0 + kc);
        As[(kc + 0) * 65 + m] = v.x;
        As[(kc + 1) * 65 + m] = v.y;
        As[(kc + 2) * 65 + m] = v.z;
        As[(kc + 3) * 65 + m] = v.w;
    }
    for (int i = 0; i < 36; i++) {
        int idx = tid + i * 256;
        int k = idx / 36, n = idx - k * 36;
        Ws[k * 37 + n] = W[(size_t)(k0 + k) * 36 + n];
    }
    __syncthreads();

    const int m = tid & 63, ng = tid >> 6;
    const int n0 = ng * 9;
    float acc[9];
#pragma unroll
    for (int j = 0; j < 9; j++) acc[j] = 0.f;

    for (int k = 0; k < 256; k++) {
        float a = As[k * 65 + m];
#pragma unroll
        for (int j = 0; j < 9; j++) acc[j] = fmaf(a, Ws[k * 37 + n0 + j], acc[j]);
    }
#pragma unroll
    for (int j = 0; j < 9; j++) atomicAdd(&z2[m * 36 + n0 + j], acc[j]);
}

__global__ void z2_init(const float* __restrict__ bias, float* __restrict__ z2)
{
    int i = blockIdx.x * 256 + threadIdx.x;
    if (i < B_ * 36) z2[i] = bias[i % 36];
}

// fc3 (36->6) + fc4 (6->6) + relu
__global__ void fc34_kernel(const float* __restrict__ z2,
                            const float* __restrict__ w3, const float* __restrict__ b3,
                            const float* __restrict__ w4, const float* __restrict__ b4,
                            float* __restrict__ out)
{
    int m = threadIdx.x;
    if (m >= B_) return;
    float t3[6];
#pragma unroll
    for (int n = 0; n < 6; n++) {
        float s = b3[n];
        for (int k = 0; k < 36; k++) s = fmaf(z2[m * 36 + k], w3[k * 6 + n], s);
        t3[n] = s;
    }
#pragma unroll
    for (int n = 0; n < 6; n++) {
        float s = b4[n];
#pragma unroll
        for (int k = 0; k < 6; k++) s = fmaf(t3[k], w4[k * 6 + n], s);
        out[m * 6 + n] = fmaxf(s, 0.f);
    }
}

// ---------------------------------------------------------------------------
extern "C" void kernel_launch(void* const* d_in, const int* in_sizes, int n_in,
                              void* d_out, int out_size)
{
    const float* x     = (const float*)d_in[0];
    const float* h0    = (const float*)d_in[1];
    const float* c0    = (const float*)d_in[2];
    const float* W1    = (const float*)d_in[3];
    const float* U1    = (const float*)d_in[4];
    const float* b1    = (const float*)d_in[5];
    const float* W2    = (const float*)d_in[6];
    const float* U2    = (const float*)d_in[7];
    const float* b2    = (const float*)d_in[8];
    const float* fc1_w = (const float*)d_in[9];
    const float* fc1_b = (const float*)d_in[10];
    const float* fc2_w = (const float*)d_in[11];
    const float* fc2_b = (const float*)d_in[12];
    const float* fc3_w = (const float*)d_in[13];
    const float* fc3_b = (const float*)d_in[14];
    const float* fc4_w = (const float*)d_in[15];
    const float* fc4_b = (const float*)d_in[16];
    float* out = (float*)d_out;

    float *xw, *c, *z1, *z2;
    int* cnt;
    __half *h16, *x16, *W1_16, *U1_16, *W2_16, *U2_16, *fc1w16, *ys1_16, *ys2_16;
    cudaGetSymbolAddress((void**)&xw, g_xw);
    cudaGetSymbolAddress((void**)&c, g_c);
    cudaGetSymbolAddress((void**)&h16, g_h16);
    cudaGetSymbolAddress((void**)&x16, g_x16);
    cudaGetSymbolAddress((void**)&W1_16, g_W1_16);
    cudaGetSymbolAddress((void**)&U1_16, g_U1_16);
    cudaGetSymbolAddress((void**)&W2_16, g_W2_16);
    cudaGetSymbolAddress((void**)&U2_16, g_U2_16);
    cudaGetSymbolAddress((void**)&fc1w16, g_fc1w16);
    cudaGetSymbolAddress((void**)&ys1_16, g_ys1_16);
    cudaGetSymbolAddress((void**)&ys2_16, g_ys2_16);
    cudaGetSymbolAddress((void**)&z1, g_z1);
    cudaGetSymbolAddress((void**)&z2, g_z2);
    cudaGetSymbolAddress((void**)&cnt, g_cnt);

    static bool attr_done = false;
    if (!attr_done) {
        cudaFuncSetAttribute(lstm_layer_tc9,
                             cudaFuncAttributeMaxDynamicSharedMemorySize, LSTM_SMEM);
        cudaFuncSetAttribute(fc2_split,
                             cudaFuncAttributeMaxDynamicSharedMemorySize, FC2_SMEM);
        attr_done = true;
    }

    const int MT = B_ * T_;  // 16384

    auto conv = [](const float* src, __half* dst, int n) {
        f32_to_f16<<<(n / 4 + 255) / 256, 256>>>(src, dst, n);
    };

    conv(x, x16, MT * D_);
    conv(W1, W1_16, D_ * G4);
    hgemm<<<dim3(G4 / 128, MT / 128), 256>>>(x16, W1_16, b1, xw, MT, G4, D_);
    conv(U1, U1_16, H_ * G4);
    init_all<<<BH / 256, 256>>>(h0, h16, cnt);
    lstm_layer_tc9<<<128, 256, LSTM_SMEM>>>(U1_16, xw, c0, c, h16, ys1_16, cnt);

    conv(W2, W2_16, H_ * G4);
    conv(U2, U2_16, H_ * G4);
    conv(fc1_w, fc1w16, H_ * (H_ / 2));

    // xw = ys1 @ W2 + b2
    hgemm<<<dim3(G4 / 128, MT / 128), 256>>>(ys1_16, W2_16, b2, xw, MT, G4, H_);

    // LSTM layer 2 (h16 buf0 / c carry over — matches reference seeding)
    lstm_layer_tc9<<<128, 256, LSTM_SMEM>>>(U2_16, xw, c, c, h16, ys2_16,
                                            cnt + T_ * 2);

    // z1 = ys2 @ fc1_w + fc1_b
    hgemm<<<dim3((H_ / 2) / 128, MT / 128), 256>>>(ys2_16, fc1w16, fc1_b, z1,
                                                   MT, H_ / 2, H_);

    // fc2: z2 = bias, then split-K accumulate
    z2_init<<<(B_ * 36 + 255) / 256, 256>>>(fc2_b, z2);
    fc2_split<<<512, 256, FC2_SMEM>>>(z1, fc2_w, z2);

    // fc3 + fc4 + relu -> out (64, 6)
    fc34_kernel<<<1, 64>>>(z2, fc3_w, fc3_b, fc4_w, fc4_b, out);
}

// round 15
// speedup vs baseline: 1.2309x; 1.0724x over previous
#include <cuda_runtime.h>
#include <cuda_fp16.h>
#include <math.h>
#include <stdint.h>

// Problem constants
constexpr int B_ = 64;
constexpr int T_ = 256;
constexpr int D_ = 512;
constexpr int H_ = 1024;
constexpr int G4 = 4 * H_;         // 4096
constexpr int BH = B_ * H_;        // 65536

// ------------------------- device scratch (no allocs) ----------------------
__device__ float  g_xw[(size_t)B_ * T_ * G4];        // (B*T, 4H) fp32
__device__ float  g_c[BH];                           // cell state fp32
__device__ __half g_h16[2 * BH];                     // double-buffered hidden
__device__ __half g_x16[(size_t)B_ * T_ * D_];
__device__ __half g_W1_16[(size_t)D_ * G4];
__device__ __half g_U1_16[(size_t)H_ * G4];
__device__ __half g_W2_16[(size_t)H_ * G4];
__device__ __half g_U2_16[(size_t)H_ * G4];
__device__ __half g_fc1w16[(size_t)H_ * (H_ / 2)];
__device__ __half g_ys1_16[(size_t)B_ * T_ * H_];
__device__ __half g_ys2_16[(size_t)B_ * T_ * H_];
__device__ float  g_z1[(size_t)B_ * T_ * (H_ / 2)];
__device__ float  g_z2[B_ * 36];
__device__ int    g_cnt[2 * T_ * 2 * 4];             // [layer][t][bh][q] arrivals

// ------------------------------ PTX helpers --------------------------------
__device__ __forceinline__ uint32_t smem_u32(const void* p) {
    uint32_t a;
    asm("{ .reg .u64 t; cvta.to.shared.u64 t, %1; cvt.u32.u64 %0, t; }"
        : "=r"(a) : "l"(p));
    return a;
}
__device__ __forceinline__ void cp_async16(uint32_t dst, const void* src) {
    asm volatile("cp.async.cg.shared.global [%0], [%1], 16;" :: "r"(dst), "l"(src));
}
__device__ __forceinline__ void cp_commit() {
    asm volatile("cp.async.commit_group;");
}
template <int N> __device__ __forceinline__ void cp_wait_n() {
    asm volatile("cp.async.wait_group %0;" :: "n"(N));
}
__device__ __forceinline__ void ldmatrix_x4(uint32_t* r, uint32_t addr) {
    asm volatile("ldmatrix.sync.aligned.m8n8.x4.shared.b16 {%0,%1,%2,%3}, [%4];"
                 : "=r"(r[0]), "=r"(r[1]), "=r"(r[2]), "=r"(r[3]) : "r"(addr));
}
__device__ __forceinline__ void ldmatrix_x4t(uint32_t* r, uint32_t addr) {
    asm volatile("ldmatrix.sync.aligned.m8n8.x4.trans.shared.b16 {%0,%1,%2,%3}, [%4];"
                 : "=r"(r[0]), "=r"(r[1]), "=r"(r[2]), "=r"(r[3]) : "r"(addr));
}
__device__ __forceinline__ void ldmatrix_x2t(uint32_t* r, uint32_t addr) {
    asm volatile("ldmatrix.sync.aligned.m8n8.x2.trans.shared.b16 {%0,%1}, [%2];"
                 : "=r"(r[0]), "=r"(r[1]) : "r"(addr));
}
__device__ __forceinline__ void mma16816(float* d, const uint32_t* a, const uint32_t* b) {
    asm volatile(
        "mma.sync.aligned.m16n8k16.row.col.f32.f16.f16.f32 "
        "{%0,%1,%2,%3},{%4,%5,%6,%7},{%8,%9},{%0,%1,%2,%3};"
        : "+f"(d[0]), "+f"(d[1]), "+f"(d[2]), "+f"(d[3])
        : "r"(a[0]), "r"(a[1]), "r"(a[2]), "r"(a[3]), "r"(b[0]), "r"(b[1]));
}
// acquire load (volatile asm — cannot be hoisted or deleted)
__device__ __forceinline__ int ld_acquire_gpu(const int* p) {
    int v;
    asm volatile("ld.acquire.gpu.global.s32 %0, [%1];" : "=r"(v) : "l"(p) : "memory");
    return v;
}
// release reduction
__device__ __forceinline__ void red_release_add(int* p, int v) {
    asm volatile("red.release.gpu.global.add.s32 [%0], %1;" :: "l"(p), "r"(v) : "memory");
}

// fast gate math: MUFU-based, rel err ~2e-7 (invisible vs fp16 5.6e-4)
__device__ __forceinline__ float fast_sigmoid(float x) {
    return __fdividef(1.f, 1.f + __expf(-x));
}
__device__ __forceinline__ float fast_tanh(float x) {
    return 1.f - __fdividef(2.f, __expf(2.f * x) + 1.f);
}

// ---------------------------------------------------------------------------
__global__ void f32_to_f16(const float* __restrict__ in, __half* __restrict__ out, int n)
{
    int i4 = (blockIdx.x * 256 + threadIdx.x) * 4;
    if (i4 < n) {
        float4 v = *reinterpret_cast<const float4*>(in + i4);
        *reinterpret_cast<__half2*>(out + i4)     = __floats2half2_rn(v.x, v.y);
        *reinterpret_cast<__half2*>(out + i4 + 2) = __floats2half2_rn(v.z, v.w);
    }
}

// seed h16 buf0 from h0, zero BOTH layers' arrival counters
__global__ void init_all(const float* __restrict__ h0, __half* __restrict__ h16,
                         int* __restrict__ cnt)
{
    int i = blockIdx.x * 256 + threadIdx.x;
    if (i < BH) h16[i] = __float2half_rn(h0[i]);
    if (i < 2 * T_ * 2 * 4) cnt[i] = 0;
}

// ---------------------------------------------------------------------------
// HGEMM: C_fp32(M,N) = A_fp16(M,K) @ B_fp16(K,N) + bias(N)
// 128x128x32 tile, 256 threads, THREE-stage cp.async pipeline.
// ---------------------------------------------------------------------------
__global__ void __launch_bounds__(256) hgemm(
    const __half* __restrict__ A, const __half* __restrict__ Bm,
    const float* __restrict__ bias, float* __restrict__ C,
    int M, int N, int K)
{
    __shared__ __half As[3][128 * 40];
    __shared__ __half Bs[3][32 * 136];

    const int tid = threadIdx.x;
    const int w = tid >> 5, lane = tid & 31;
    const int bm = blockIdx.y * 128, bn = blockIdx.x * 128;
    const int wm = (w >> 2) * 64, wn = (w & 3) * 32;
    const uint32_t AsU = smem_u32(As), BsU = smem_u32(Bs);

    float acc[4][4][4];
#pragma unroll
    for (int i = 0; i < 4; i++)
#pragma unroll
        for (int j = 0; j < 4; j++)
#pragma unroll
            for (int e = 0; e < 4; e++) acc[i][j][e] = 0.f;

    const int nk = K / 32;

#define LOAD_TILE(kt, buf)                                                        \
    {                                                                             \
        int k0 = (kt) * 32;                                                       \
        _Pragma("unroll")                                                         \
        for (int e = 0; e < 2; e++) {                                             \
            int idx = tid + e * 256;                                              \
            int r = idx >> 2, ch = idx & 3;                                       \
            cp_async16(AsU + ((buf) * 5120 + r * 40 + ch * 8) * 2,                \
                       A + (size_t)(bm + r) * K + k0 + ch * 8);                   \
        }                                                                         \
        _Pragma("unroll")                                                         \
        for (int e = 0; e < 2; e++) {                                             \
            int idx = tid + e * 256;                                              \
            int r = idx >> 4, ch = idx & 15;                                      \
            cp_async16(BsU + ((buf) * 4352 + r * 136 + ch * 8) * 2,               \
                       Bm + (size_t)(k0 + r) * N + bn + ch * 8);                  \
        }                                                                         \
        cp_commit();                                                              \
    }

    LOAD_TILE(0, 0)
    if (nk > 1) LOAD_TILE(1, 1)

    for (int kt = 0; kt < nk; kt++) {
        int buf = kt % 3;
        if (kt + 1 < nk) cp_wait_n<1>(); else cp_wait_n<0>();
        __syncthreads();
        if (kt + 2 < nk) LOAD_TILE(kt + 2, (kt + 2) % 3)

#pragma unroll
        for (int ks = 0; ks < 2; ks++) {
            uint32_t bfr[4][2];
#pragma unroll
            for (int nf = 0; nf < 4; nf++)
                ldmatrix_x2t(bfr[nf],
                    BsU + (buf * 4352 + (ks * 16 + (lane & 15)) * 136 + wn + nf * 8) * 2);
#pragma unroll
            for (int mf = 0; mf < 4; mf++) {
                uint32_t afr[4];
                ldmatrix_x4(afr,
                    AsU + (buf * 5120 + (wm + mf * 16 + (lane & 15)) * 40
                           + ks * 16 + ((lane >> 4) * 8)) * 2);
#pragma unroll
                for (int nf = 0; nf < 4; nf++) mma16816(acc[mf][nf], afr, bfr[nf]);
            }
        }
        __syncthreads();
    }
#undef LOAD_TILE

    const int g = lane >> 2, t4 = lane & 3;
#pragma unroll
    for (int mf = 0; mf < 4; mf++)
#pragma unroll
        for (int nf = 0; nf < 4; nf++) {
            int row0 = bm + wm + mf * 16 + g;
            int col = bn + wn + nf * 8 + t4 * 2;
            float b0 = bias ? bias[col] : 0.f;
            float b1 = bias ? bias[col + 1] : 0.f;
            C[(size_t)row0 * N + col]           = acc[mf][nf][0] + b0;
            C[(size_t)row0 * N + col + 1]       = acc[mf][nf][1] + b1;
            C[(size_t)(row0 + 8) * N + col]     = acc[mf][nf][2] + b0;
            C[(size_t)(row0 + 8) * N + col + 1] = acc[mf][nf][3] + b1;
        }
}

// ---------------------------------------------------------------------------
// Persistent tensor-core LSTM v10 — split-K warps + PER-WARP decoupled waits.
// 128 CTAs = 64 j-groups x 2 batch halves; CTA tile M=32, N=64, K=1024.
// Warp w owns k-slice [128w,128w+128) = h-chunk q=w>>1 (256 cols), produced
// by exactly 16 CTAs. Counters cnt[t][bh][q] (target 16).
//  - warp w: lane0 acquire-polls ONLY its chunk counter, __syncwarp, then
//    stages its 8KB slice (own cp.async group) and runs its mma — fully
//    decoupled from other warps/chunks. NO loop-top block barrier.
//  - post-mma block barrier: joins all warps' waits (=> any h-write at step
//    t is after ALL 4 chunk counters of t-1 hit 16 = all 64 same-bh CTAs
//    arrived = their t-1 staging reads done -> double-buffer WAR safe) and
//    protects the partial/A_s alias.
//  - partial write, barrier, reduce+gates+h/ys store, barrier, tid0 release
//    to cnt[t][bh][qself] (qself=jg>>4) — one release per CTA-step.
// ---------------------------------------------------------------------------
constexpr int U_BYTES    = 1024 * 72 * 2;     // 147456
constexpr int PART_BYTES = 8 * 32 * 66 * 4;   // 67584 (A_s 66048 aliases inside)
constexpr int LSTM_SMEM  = U_BYTES + PART_BYTES;  // 215040

__global__ void __launch_bounds__(256) lstm_layer_tc10(
    const __half* __restrict__ U16,   // (1024, 4096) fp16
    const float* __restrict__ xw,     // (B*T, 4096) fp32, rows b*T+t
    const float* __restrict__ cseed,  // (B,1024) fp32 initial cell
    float* __restrict__ cout,         // (B,1024) fp32 final cell
    __half* __restrict__ h16,         // [2][B][1024] fp16 (buf0 pre-seeded)
    __half* __restrict__ ys16,        // (B*T, 1024) fp16 out
    int* __restrict__ cnt)            // [T][2][4] arrival counters (zeroed)
{
    extern __shared__ char sm[];
    __half* U_s = (__half*)sm;                 // [1024][72]
    __half* A_s = (__half*)(sm + U_BYTES);     // [32][1032] (66048 B)
    float*  part = (float*)(sm + U_BYTES);     // [8][32][66] fp32 alias
    const uint32_t U_u = smem_u32(U_s);
    const uint32_t A_u = smem_u32(A_s);

    const int tid = threadIdx.x;
    const int w = tid >> 5, lane = tid & 31;
    const int jg = blockIdx.x >> 1;            // 0..63
    const int bh = blockIdx.x & 1;             // batch half
    const int j0 = jg * 16;
    const int kb = w * 128;                    // this warp's k-slice base
    const int qw = w >> 1;                     // chunk this warp consumes
    const int qself = jg >> 4;                 // chunk this CTA produces

    // ---- preload U slice: U_s[k][jp*8 + 2*gate + jj] = U16[k][gate*H + j0 + 2*jp + jj]
    for (int i = 0; i < 128; i++) {
        int idx = tid + i * 256;
        int k = idx >> 5;
        int gate = (idx >> 3) & 3;
        int jp = idx & 7;
        *reinterpret_cast<__half2*>(U_s + k * 72 + jp * 8 + 2 * gate) =
            *reinterpret_cast<const __half2*>(U16 + (size_t)k * G4 + gate * H_ + j0 + 2 * jp);
    }
    __syncthreads();

    // epilogue cell ownership: thread -> (local row eb, j-pair ejp), 2 cells
    const int eb = tid >> 3;                   // 0..31
    const int ejp = tid & 7;                   // 0..7
    const int bloc = bh * 32 + eb;
    float2 creg = *reinterpret_cast<const float2*>(cseed + (size_t)bloc * H_ + j0 + 2 * ejp);

    for (int t = 0; t < T_; t++) {
        // prefetch xw for this thread's two cells (independent of h)
        float2 xg[4];
        {
            size_t xbase = ((size_t)bloc * T_ + t) * (size_t)G4 + j0 + 2 * ejp;
#pragma unroll
            for (int gg = 0; gg < 4; gg++)
                xg[gg] = __ldg(reinterpret_cast<const float2*>(xw + xbase + (size_t)gg * H_));
        }

        // PER-WARP wait: only this warp's chunk producers (16 CTAs)
        if (t > 0) {
            if (lane == 0) {
                const int* cp = &cnt[((t - 1) * 2 + bh) * 4 + qw];
                while ((unsigned)ld_acquire_gpu(cp) < 16u) { }
            }
            __syncwarp();
        }

        const __half* hg = h16 + (size_t)(t & 1) * BH + (size_t)bh * 32 * H_;

        // warp-local staging of OWN k-slice: 32 rows x 128 cols = 8KB
#pragma unroll
        for (int i = 0; i < 16; i++) {
            int idx = i * 32 + lane;
            int r = idx >> 4;
            int ch = idx & 15;
            cp_async16(A_u + (r * 1032 + kb + ch * 8) * 2,
                       hg + (size_t)r * H_ + kb + ch * 8);
        }
        cp_commit();
        cp_wait_n<0>();                // warp-local; no block barrier needed

        float acc[2][8][4];
#pragma unroll
        for (int mg = 0; mg < 2; mg++)
#pragma unroll
            for (int ng = 0; ng < 8; ng++)
#pragma unroll
                for (int e = 0; e < 4; e++) acc[mg][ng][e] = 0.f;

#pragma unroll
        for (int ks2 = 0; ks2 < 4; ks2++) {
            int kk = kb + ks2 * 32;
            uint32_t a0[4], a1[4], a2[4], a3[4];
            ldmatrix_x4(a0, A_u + (((lane & 15)) * 1032 + kk + (lane >> 4) * 8) * 2);
            ldmatrix_x4(a1, A_u + ((16 + (lane & 15)) * 1032 + kk + (lane >> 4) * 8) * 2);
            ldmatrix_x4(a2, A_u + (((lane & 15)) * 1032 + kk + 16 + (lane >> 4) * 8) * 2);
            ldmatrix_x4(a3, A_u + ((16 + (lane & 15)) * 1032 + kk + 16 + (lane >> 4) * 8) * 2);
#pragma unroll
            for (int ng = 0; ng < 8; ng++) {
                uint32_t bq[4];
                ldmatrix_x4t(bq, U_u + ((kk + lane) * 72 + ng * 8) * 2);
                mma16816(acc[0][ng], a0, bq);
                mma16816(acc[1][ng], a1, bq);
                mma16816(acc[0][ng], a2, bq + 2);
                mma16816(acc[1][ng], a3, bq + 2);
            }
        }
        __syncthreads();   // joins all warps' waits; A_s reads done -> alias ok

        // write partials: part[w][row][col], rows padded to 66 floats
        {
            float* pw = part + w * (32 * 66);
            const int pr = lane >> 2, pc = (lane & 3) * 2;
#pragma unroll
            for (int mg = 0; mg < 2; mg++)
#pragma unroll
                for (int ng = 0; ng < 8; ng++) {
                    int row = mg * 16 + pr;
                    *reinterpret_cast<float2*>(pw + row * 66 + ng * 8 + pc) =
                        make_float2(acc[mg][ng][0], acc[mg][ng][1]);
                    *reinterpret_cast<float2*>(pw + (row + 8) * 66 + ng * 8 + pc) =
                        make_float2(acc[mg][ng][2], acc[mg][ng][3]);
                }
        }
        __syncthreads();

        // reduce 8 warp-partials + cell update (thread: row eb, cols ejp*8+2g+e)
        {
            float2 gt[4];
#pragma unroll
            for (int gg = 0; gg < 4; gg++) {
                int c = ejp * 8 + 2 * gg;
                float2 s = make_float2(0.f, 0.f);
#pragma unroll
                for (int ww = 0; ww < 8; ww++) {
                    float2 v = *reinterpret_cast<const float2*>(
                        part + ww * (32 * 66) + eb * 66 + c);
                    s.x += v.x; s.y += v.y;
                }
                gt[gg] = s;
            }

            float iva = gt[0].x + xg[0].x;
            float ivb = gt[0].y + xg[0].y;
            float fva = gt[1].x + xg[1].x;
            float fvb = gt[1].y + xg[1].y;
            float gva = gt[2].x + xg[2].x;
            float gvb = gt[2].y + xg[2].y;
            float ova = gt[3].x + xg[3].x;
            float ovb = gt[3].y + xg[3].y;

            float cna = fast_sigmoid(fva) * creg.x + fast_sigmoid(iva) * fast_tanh(gva);
            float cnb = fast_sigmoid(fvb) * creg.y + fast_sigmoid(ivb) * fast_tanh(gvb);
            float hna = fast_sigmoid(ova) * fast_tanh(cna);
            float hnb = fast_sigmoid(ovb) * fast_tanh(cnb);
            creg.x = cna; creg.y = cnb;

            __half2 h2 = __floats2half2_rn(hna, hnb);
            *reinterpret_cast<__half2*>(
                h16 + (size_t)((t + 1) & 1) * BH + (size_t)bloc * H_ + j0 + 2 * ejp) = h2;
            *reinterpret_cast<__half2*>(
                ys16 + ((size_t)bloc * T_ + t) * (size_t)H_ + j0 + 2 * ejp) = h2;
        }

        // arrive: bar.sync orders all threads' h-stores (and partial reads —
        // protects A_s alias for next step's staging) before the release
        __syncthreads();
        if (tid == 0) red_release_add(&cnt[(t * 2 + bh) * 4 + qself], 1);
    }

    // write back final cell state
    *reinterpret_cast<float2*>(cout + (size_t)bloc * H_ + j0 + 2 * ejp) = creg;
}

// ---------------------------------------------------------------------------
// fc2 split-K: z2(64,36) += z1(64,131072) @ W(131072,36); z2 pre-seeded w/ bias
// ---------------------------------------------------------------------------
constexpr int FC2_SMEM = 256 * 65 * 4 + 256 * 37 * 4;  // 104448

__global__ void __launch_bounds__(256) fc2_split(
    const float* __restrict__ z1, const float* __restrict__ W,
    float* __restrict__ z2)
{
    extern __shared__ float smf[];
    float* As = smf;                 // [256 k][65 m-pad]
    float* Ws = smf + 256 * 65;      // [256 k][37 n-pad]
    const int k0 = blockIdx.x * 256;
    const int tid = threadIdx.x;

    for (int i = 0; i < 16; i++) {
        int idx = tid + i * 256;
        int m = idx >> 6, kc = (idx & 63) * 4;
        float4 v = *reinterpret_cast<const float4*>(z1 + (size_t)m * 131072 + k0 + kc);
        As[(kc + 0) * 65 + m] = v.x;
        As[(kc + 1) * 65 + m] = v.y;
        As[(kc + 2) * 65 + m] = v.z;
        As[(kc + 3) * 65 + m] = v.w;
    }
    for (int i = 0; i < 36; i++) {
        int idx = tid + i * 256;
        int k = idx / 36, n = idx - k * 36;
        Ws[k * 37 + n] = W[(size_t)(k0 + k) * 36 + n];
    }
    __syncthreads();

    const int m = tid & 63, ng = tid >> 6;
    const int n0 = ng * 9;
    float acc[9];
#pragma unroll
    for (int j = 0; j < 9; j++) acc[j] = 0.f;

    for (int k = 0; k < 256; k++) {
        float a = As[k * 65 + m];
#pragma unroll
        for (int j = 0; j < 9; j++) acc[j] = fmaf(a, Ws[k * 37 + n0 + j], acc[j]);
    }
#pragma unroll
    for (int j = 0; j < 9; j++) atomicAdd(&z2[m * 36 + n0 + j], acc[j]);
}

__global__ void z2_init(const float* __restrict__ bias, float* __restrict__ z2)
{
    int i = blockIdx.x * 256 + threadIdx.x;
    if (i < B_ * 36) z2[i] = bias[i % 36];
}

// fc3 (36->6) + fc4 (6->6) + relu
__global__ void fc34_kernel(const float* __restrict__ z2,
                            const float* __restrict__ w3, const float* __restrict__ b3,
                            const float* __restrict__ w4, const float* __restrict__ b4,
                            float* __restrict__ out)
{
    int m = threadIdx.x;
    if (m >= B_) return;
    float t3[6];
#pragma unroll
    for (int n = 0; n < 6; n++) {
        float s = b3[n];
        for (int k = 0; k < 36; k++) s = fmaf(z2[m * 36 + k], w3[k * 6 + n], s);
        t3[n] = s;
    }
#pragma unroll
    for (int n = 0; n < 6; n++) {
        float s = b4[n];
#pragma unroll
        for (int k = 0; k < 6; k++) s = fmaf(t3[k], w4[k * 6 + n], s);
        out[m * 6 + n] = fmaxf(s, 0.f);
    }
}

// ---------------------------------------------------------------------------
extern "C" void kernel_launch(void* const* d_in, const int* in_sizes, int n_in,
                              void* d_out, int out_size)
{
    const float* x     = (const float*)d_in[0];
    const float* h0    = (const float*)d_in[1];
    const float* c0    = (const float*)d_in[2];
    const float* W1    = (const float*)d_in[3];
    const float* U1    = (const float*)d_in[4];
    const float* b1    = (const float*)d_in[5];
    const float* W2    = (const float*)d_in[6];
    const float* U2    = (const float*)d_in[7];
    const float* b2    = (const float*)d_in[8];
    const float* fc1_w = (const float*)d_in[9];
    const float* fc1_b = (const float*)d_in[10];
    const float* fc2_w = (const float*)d_in[11];
    const float* fc2_b = (const float*)d_in[12];
    const float* fc3_w = (const float*)d_in[13];
    const float* fc3_b = (const float*)d_in[14];
    const float* fc4_w = (const float*)d_in[15];
    const float* fc4_b = (const float*)d_in[16];
    float* out = (float*)d_out;

    float *xw, *c, *z1, *z2;
    int* cnt;
    __half *h16, *x16, *W1_16, *U1_16, *W2_16, *U2_16, *fc1w16, *ys1_16, *ys2_16;
    cudaGetSymbolAddress((void**)&xw, g_xw);
    cudaGetSymbolAddress((void**)&c, g_c);
    cudaGetSymbolAddress((void**)&h16, g_h16);
    cudaGetSymbolAddress((void**)&x16, g_x16);
    cudaGetSymbolAddress((void**)&W1_16, g_W1_16);
    cudaGetSymbolAddress((void**)&U1_16, g_U1_16);
    cudaGetSymbolAddress((void**)&W2_16, g_W2_16);
    cudaGetSymbolAddress((void**)&U2_16, g_U2_16);
    cudaGetSymbolAddress((void**)&fc1w16, g_fc1w16);
    cudaGetSymbolAddress((void**)&ys1_16, g_ys1_16);
    cudaGetSymbolAddress((void**)&ys2_16, g_ys2_16);
    cudaGetSymbolAddress((void**)&z1, g_z1);
    cudaGetSymbolAddress((void**)&z2, g_z2);
    cudaGetSymbolAddress((void**)&cnt, g_cnt);

    static bool attr_done = false;
    if (!attr_done) {
        cudaFuncSetAttribute(lstm_layer_tc10,
                             cudaFuncAttributeMaxDynamicSharedMemorySize, LSTM_SMEM);
        cudaFuncSetAttribute(fc2_split,
                             cudaFuncAttributeMaxDynamicSharedMemorySize, FC2_SMEM);
        attr_done = true;
    }

    const int MT = B_ * T_;  // 16384

    auto conv = [](const float* src, __half* dst, int n) {
        f32_to_f16<<<(n / 4 + 255) / 256, 256>>>(src, dst, n);
    };

    conv(x, x16, MT * D_);
    conv(W1, W1_16, D_ * G4);
    hgemm<<<dim3(G4 / 128, MT / 128), 256>>>(x16, W1_16, b1, xw, MT, G4, D_);
    conv(U1, U1_16, H_ * G4);
    init_all<<<BH / 256, 256>>>(h0, h16, cnt);
    lstm_layer_tc10<<<128, 256, LSTM_SMEM>>>(U1_16, xw, c0, c, h16, ys1_16, cnt);

    conv(W2, W2_16, H_ * G4);
    conv(U2, U2_16, H_ * G4);
    conv(fc1_w, fc1w16, H_ * (H_ / 2));

    // xw = ys1 @ W2 + b2
    hgemm<<<dim3(G4 / 128, MT / 128), 256>>>(ys1_16, W2_16, b2, xw, MT, G4, H_);

    // LSTM layer 2 (h16 buf0 / c carry over — matches reference seeding)
    lstm_layer_tc10<<<128, 256, LSTM_SMEM>>>(U2_16, xw, c, c, h16, ys2_16,
                                             cnt + T_ * 2 * 4);

    // z1 = ys2 @ fc1_w + fc1_b
    hgemm<<<dim3((H_ / 2) / 128, MT / 128), 256>>>(ys2_16, fc1w16, fc1_b, z1,
                                                   MT, H_ / 2, H_);

    // fc2: z2 = bias, then split-K accumulate
    z2_init<<<(B_ * 36 + 255) / 256, 256>>>(fc2_b, z2);
    fc2_split<<<512, 256, FC2_SMEM>>>(z1, fc2_w, z2);

    // fc3 + fc4 + relu -> out (64, 6)
    fc34_kernel<<<1, 64>>>(z2, fc3_w, fc3_b, fc4_w, fc4_b, out);
}

// round 16
// speedup vs baseline: 1.3711x; 1.1139x over previous
#include <cuda_runtime.h>
#include <cuda_fp16.h>
#include <math.h>
#include <stdint.h>

// Problem constants
constexpr int B_ = 64;
constexpr int T_ = 256;
constexpr int D_ = 512;
constexpr int H_ = 1024;
constexpr int G4 = 4 * H_;         // 4096
constexpr int BH = B_ * H_;        // 65536

// ------------------------- device scratch (no allocs) ----------------------
__device__ float  g_xw[(size_t)B_ * T_ * G4];        // (B*T, 4H) fp32
__device__ float  g_c[BH];                           // cell state fp32
__device__ __half g_h16[2 * BH];                     // double-buffered hidden
__device__ __half g_x16[(size_t)B_ * T_ * D_];
__device__ __half g_W1_16[(size_t)D_ * G4];
__device__ __half g_U1_16[(size_t)H_ * G4];
__device__ __half g_W2_16[(size_t)H_ * G4];
__device__ __half g_U2_16[(size_t)H_ * G4];
__device__ __half g_fc1w16[(size_t)H_ * (H_ / 2)];
__device__ __half g_ys1_16[(size_t)B_ * T_ * H_];
__device__ __half g_ys2_16[(size_t)B_ * T_ * H_];
__device__ float  g_z1[(size_t)B_ * T_ * (H_ / 2)];
__device__ float  g_z2[B_ * 36];
__device__ int    g_cnt[2 * T_ * 2 * 4];             // [layer][t][bh][q] arrivals

// ------------------------------ PTX helpers --------------------------------
__device__ __forceinline__ uint32_t smem_u32(const void* p) {
    uint32_t a;
    asm("{ .reg .u64 t; cvta.to.shared.u64 t, %1; cvt.u32.u64 %0, t; }"
        : "=r"(a) : "l"(p));
    return a;
}
__device__ __forceinline__ void cp_async16(uint32_t dst, const void* src) {
    asm volatile("cp.async.cg.shared.global [%0], [%1], 16;" :: "r"(dst), "l"(src));
}
__device__ __forceinline__ void cp_commit() {
    asm volatile("cp.async.commit_group;");
}
template <int N> __device__ __forceinline__ void cp_wait_n() {
    asm volatile("cp.async.wait_group %0;" :: "n"(N));
}
__device__ __forceinline__ void ldmatrix_x4(uint32_t* r, uint32_t addr) {
    asm volatile("ldmatrix.sync.aligned.m8n8.x4.shared.b16 {%0,%1,%2,%3}, [%4];"
                 : "=r"(r[0]), "=r"(r[1]), "=r"(r[2]), "=r"(r[3]) : "r"(addr));
}
__device__ __forceinline__ void ldmatrix_x4t(uint32_t* r, uint32_t addr) {
    asm volatile("ldmatrix.sync.aligned.m8n8.x4.trans.shared.b16 {%0,%1,%2,%3}, [%4];"
                 : "=r"(r[0]), "=r"(r[1]), "=r"(r[2]), "=r"(r[3]) : "r"(addr));
}
__device__ __forceinline__ void ldmatrix_x2t(uint32_t* r, uint32_t addr) {
    asm volatile("ldmatrix.sync.aligned.m8n8.x2.trans.shared.b16 {%0,%1}, [%2];"
                 : "=r"(r[0]), "=r"(r[1]) : "r"(addr));
}
__device__ __forceinline__ void mma16816(float* d, const uint32_t* a, const uint32_t* b) {
    asm volatile(
        "mma.sync.aligned.m16n8k16.row.col.f32.f16.f16.f32 "
        "{%0,%1,%2,%3},{%4,%5,%6,%7},{%8,%9},{%0,%1,%2,%3};"
        : "+f"(d[0]), "+f"(d[1]), "+f"(d[2]), "+f"(d[3])
        : "r"(a[0]), "r"(a[1]), "r"(a[2]), "r"(a[3]), "r"(b[0]), "r"(b[1]));
}
// acquire load (volatile asm — cannot be hoisted or deleted)
__device__ __forceinline__ int ld_acquire_gpu(const int* p) {
    int v;
    asm volatile("ld.acquire.gpu.global.s32 %0, [%1];" : "=r"(v) : "l"(p) : "memory");
    return v;
}
// release reduction
__device__ __forceinline__ void red_release_add(int* p, int v) {
    asm volatile("red.release.gpu.global.add.s32 [%0], %1;" :: "l"(p), "r"(v) : "memory");
}

// fast gate math: MUFU-based, rel err ~2e-7 (invisible vs fp16 5.6e-4)
__device__ __forceinline__ float fast_sigmoid(float x) {
    return __fdividef(1.f, 1.f + __expf(-x));
}
__device__ __forceinline__ float fast_tanh(float x) {
    return 1.f - __fdividef(2.f, __expf(2.f * x) + 1.f);
}

// ---------------------------------------------------------------------------
__global__ void f32_to_f16(const float* __restrict__ in, __half* __restrict__ out, int n)
{
    int i4 = (blockIdx.x * 256 + threadIdx.x) * 4;
    if (i4 < n) {
        float4 v = *reinterpret_cast<const float4*>(in + i4);
        *reinterpret_cast<__half2*>(out + i4)     = __floats2half2_rn(v.x, v.y);
        *reinterpret_cast<__half2*>(out + i4 + 2) = __floats2half2_rn(v.z, v.w);
    }
}

// seed h16 buf0 from h0, zero BOTH layers' arrival counters
__global__ void init_all(const float* __restrict__ h0, __half* __restrict__ h16,
                         int* __restrict__ cnt)
{
    int i = blockIdx.x * 256 + threadIdx.x;
    if (i < BH) h16[i] = __float2half_rn(h0[i]);
    if (i < 2 * T_ * 2 * 4) cnt[i] = 0;
}

// ---------------------------------------------------------------------------
// HGEMM: C_fp32(M,N) = A_fp16(M,K) @ B_fp16(K,N) + bias(N)
// 128x128x32 tile, 256 threads, THREE-stage cp.async pipeline.
// ---------------------------------------------------------------------------
__global__ void __launch_bounds__(256) hgemm(
    const __half* __restrict__ A, const __half* __restrict__ Bm,
    const float* __restrict__ bias, float* __restrict__ C,
    int M, int N, int K)
{
    __shared__ __half As[3][128 * 40];
    __shared__ __half Bs[3][32 * 136];

    const int tid = threadIdx.x;
    const int w = tid >> 5, lane = tid & 31;
    const int bm = blockIdx.y * 128, bn = blockIdx.x * 128;
    const int wm = (w >> 2) * 64, wn = (w & 3) * 32;
    const uint32_t AsU = smem_u32(As), BsU = smem_u32(Bs);

    float acc[4][4][4];
#pragma unroll
    for (int i = 0; i < 4; i++)
#pragma unroll
        for (int j = 0; j < 4; j++)
#pragma unroll
            for (int e = 0; e < 4; e++) acc[i][j][e] = 0.f;

    const int nk = K / 32;

#define LOAD_TILE(kt, buf)                                                        \
    {                                                                             \
        int k0 = (kt) * 32;                                                       \
        _Pragma("unroll")                                                         \
        for (int e = 0; e < 2; e++) {                                             \
            int idx = tid + e * 256;                                              \
            int r = idx >> 2, ch = idx & 3;                                       \
            cp_async16(AsU + ((buf) * 5120 + r * 40 + ch * 8) * 2,                \
                       A + (size_t)(bm + r) * K + k0 + ch * 8);                   \
        }                                                                         \
        _Pragma("unroll")                                                         \
        for (int e = 0; e < 2; e++) {                                             \
            int idx = tid + e * 256;                                              \
            int r = idx >> 4, ch = idx & 15;                                      \
            cp_async16(BsU + ((buf) * 4352 + r * 136 + ch * 8) * 2,               \
                       Bm + (size_t)(k0 + r) * N + bn + ch * 8);                  \
        }                                                                         \
        cp_commit();                                                              \
    }

    LOAD_TILE(0, 0)
    if (nk > 1) LOAD_TILE(1, 1)

    for (int kt = 0; kt < nk; kt++) {
        int buf = kt % 3;
        if (kt + 1 < nk) cp_wait_n<1>(); else cp_wait_n<0>();
        __syncthreads();
        if (kt + 2 < nk) LOAD_TILE(kt + 2, (kt + 2) % 3)

#pragma unroll
        for (int ks = 0; ks < 2; ks++) {
            uint32_t bfr[4][2];
#pragma unroll
            for (int nf = 0; nf < 4; nf++)
                ldmatrix_x2t(bfr[nf],
                    BsU + (buf * 4352 + (ks * 16 + (lane & 15)) * 136 + wn + nf * 8) * 2);
#pragma unroll
            for (int mf = 0; mf < 4; mf++) {
                uint32_t afr[4];
                ldmatrix_x4(afr,
                    AsU + (buf * 5120 + (wm + mf * 16 + (lane & 15)) * 40
                           + ks * 16 + ((lane >> 4) * 8)) * 2);
#pragma unroll
                for (int nf = 0; nf < 4; nf++) mma16816(acc[mf][nf], afr, bfr[nf]);
            }
        }
        __syncthreads();
    }
#undef LOAD_TILE

    const int g = lane >> 2, t4 = lane & 3;
#pragma unroll
    for (int mf = 0; mf < 4; mf++)
#pragma unroll
        for (int nf = 0; nf < 4; nf++) {
            int row0 = bm + wm + mf * 16 + g;
            int col = bn + wn + nf * 8 + t4 * 2;
            float b0 = bias ? bias[col] : 0.f;
            float b1 = bias ? bias[col + 1] : 0.f;
            C[(size_t)row0 * N + col]           = acc[mf][nf][0] + b0;
            C[(size_t)row0 * N + col + 1]       = acc[mf][nf][1] + b1;
            C[(size_t)(row0 + 8) * N + col]     = acc[mf][nf][2] + b0;
            C[(size_t)(row0 + 8) * N + col + 1] = acc[mf][nf][3] + b1;
        }
}

// ---------------------------------------------------------------------------
// Persistent tensor-core LSTM v11 — split-K warps, per-warp decoupled waits,
// PARTIALS-IN-OWN-SLICE (2 barriers/step, down from 3).
// 128 CTAs = 64 j-groups x 2 batch halves; CTA tile M=32, N=64, K=1024.
// Warp w owns k-slice [128w,128w+128) = h-chunk q=w>>1 (16 producer CTAs).
//  - warp w: lane0 acquire-polls ONLY its chunk counter, __syncwarp, stages
//    its 8KB slice (own cp.async group, wait 0), runs its mma.
//  - KEY: warp w's A-slice (32 rows x 256B) is read ONLY by warp w, and is
//    exactly the 8KB its 32x64 fp32 partials need. Partials are written
//    into the warp's OWN slice (program-ordered after its own LDSM reads):
//    NO post-mma barrier, no separate partial region.
//      partial(w,r,c) -> A_f[r*516 + w*64 + c]   (516 fp32 = 1032-half row)
//  - barrier(1): all partials visible -> reduce + gates + h/ys stores
//  - barrier(2): all h-stores AND all reduce-reads done (protects next
//    step's staging WAR on the slice region) -> tid0 release.
//  - cross-CTA WAR (double buffer) unchanged: a CTA's epilogue h-write at
//    step t is after all 4 chunk-waits on t-1 (joined by barrier 1) =
//    all 64 same-bh CTAs released t-1 = their staging reads done.
// ---------------------------------------------------------------------------
constexpr int U_BYTES   = 1024 * 72 * 2;   // 147456
constexpr int A_BYTES   = 32 * 1032 * 2;   // 66048
constexpr int LSTM_SMEM = U_BYTES + A_BYTES;  // 213504

__global__ void __launch_bounds__(256) lstm_layer_tc11(
    const __half* __restrict__ U16,   // (1024, 4096) fp16
    const float* __restrict__ xw,     // (B*T, 4096) fp32, rows b*T+t
    const float* __restrict__ cseed,  // (B,1024) fp32 initial cell
    float* __restrict__ cout,         // (B,1024) fp32 final cell
    __half* __restrict__ h16,         // [2][B][1024] fp16 (buf0 pre-seeded)
    __half* __restrict__ ys16,        // (B*T, 1024) fp16 out
    int* __restrict__ cnt)            // [T][2][4] arrival counters (zeroed)
{
    extern __shared__ char sm[];
    __half* U_s = (__half*)sm;                 // [1024][72]
    __half* A_s = (__half*)(sm + U_BYTES);     // [32][1032] (66048 B)
    float*  A_f = (float*)(sm + U_BYTES);      // same region as fp32 [32][516]
    const uint32_t U_u = smem_u32(U_s);
    const uint32_t A_u = smem_u32(A_s);

    const int tid = threadIdx.x;
    const int w = tid >> 5, lane = tid & 31;
    const int jg = blockIdx.x >> 1;            // 0..63
    const int bh = blockIdx.x & 1;             // batch half
    const int j0 = jg * 16;
    const int kb = w * 128;                    // this warp's k-slice base
    const int qw = w >> 1;                     // chunk this warp consumes
    const int qself = jg >> 4;                 // chunk this CTA produces

    // ---- preload U slice: U_s[k][jp*8 + 2*gate + jj] = U16[k][gate*H + j0 + 2*jp + jj]
    for (int i = 0; i < 128; i++) {
        int idx = tid + i * 256;
        int k = idx >> 5;
        int gate = (idx >> 3) & 3;
        int jp = idx & 7;
        *reinterpret_cast<__half2*>(U_s + k * 72 + jp * 8 + 2 * gate) =
            *reinterpret_cast<const __half2*>(U16 + (size_t)k * G4 + gate * H_ + j0 + 2 * jp);
    }
    __syncthreads();

    // epilogue cell ownership: thread -> (local row eb, j-pair ejp), 2 cells
    const int eb = tid >> 3;                   // 0..31
    const int ejp = tid & 7;                   // 0..7
    const int bloc = bh * 32 + eb;
    float2 creg = *reinterpret_cast<const float2*>(cseed + (size_t)bloc * H_ + j0 + 2 * ejp);

    for (int t = 0; t < T_; t++) {
        // prefetch xw for this thread's two cells (independent of h)
        float2 xg[4];
        {
            size_t xbase = ((size_t)bloc * T_ + t) * (size_t)G4 + j0 + 2 * ejp;
#pragma unroll
            for (int gg = 0; gg < 4; gg++)
                xg[gg] = __ldg(reinterpret_cast<const float2*>(xw + xbase + (size_t)gg * H_));
        }

        // PER-WARP wait: only this warp's chunk producers (16 CTAs)
        if (t > 0) {
            if (lane == 0) {
                const int* cp = &cnt[((t - 1) * 2 + bh) * 4 + qw];
                while ((unsigned)ld_acquire_gpu(cp) < 16u) { }
            }
            __syncwarp();
        }

        const __half* hg = h16 + (size_t)(t & 1) * BH + (size_t)bh * 32 * H_;

        // warp-local staging of OWN k-slice: 32 rows x 128 cols = 8KB
#pragma unroll
        for (int i = 0; i < 16; i++) {
            int idx = i * 32 + lane;
            int r = idx >> 4;
            int ch = idx & 15;
            cp_async16(A_u + (r * 1032 + kb + ch * 8) * 2,
                       hg + (size_t)r * H_ + kb + ch * 8);
        }
        cp_commit();
        cp_wait_n<0>();                // warp-local; no block barrier needed

        float acc[2][8][4];
#pragma unroll
        for (int mg = 0; mg < 2; mg++)
#pragma unroll
            for (int ng = 0; ng < 8; ng++)
#pragma unroll
                for (int e = 0; e < 4; e++) acc[mg][ng][e] = 0.f;

#pragma unroll
        for (int ks2 = 0; ks2 < 4; ks2++) {
            int kk = kb + ks2 * 32;
            uint32_t a0[4], a1[4], a2[4], a3[4];
            ldmatrix_x4(a0, A_u + (((lane & 15)) * 1032 + kk + (lane >> 4) * 8) * 2);
            ldmatrix_x4(a1, A_u + ((16 + (lane & 15)) * 1032 + kk + (lane >> 4) * 8) * 2);
            ldmatrix_x4(a2, A_u + (((lane & 15)) * 1032 + kk + 16 + (lane >> 4) * 8) * 2);
            ldmatrix_x4(a3, A_u + ((16 + (lane & 15)) * 1032 + kk + 16 + (lane >> 4) * 8) * 2);
#pragma unroll
            for (int ng = 0; ng < 8; ng++) {
                uint32_t bq[4];
                ldmatrix_x4t(bq, U_u + ((kk + lane) * 72 + ng * 8) * 2);
                mma16816(acc[0][ng], a0, bq);
                mma16816(acc[1][ng], a1, bq);
                mma16816(acc[0][ng], a2, bq + 2);
                mma16816(acc[1][ng], a3, bq + 2);
            }
        }

        // write partials into OWN slice region — warp-private, no barrier:
        // this warp's LDSM reads of the region are complete (program order)
        {
            float* pw = A_f + w * 64;
            const int pr = lane >> 2, pc = (lane & 3) * 2;
#pragma unroll
            for (int mg = 0; mg < 2; mg++)
#pragma unroll
                for (int ng = 0; ng < 8; ng++) {
                    int row = mg * 16 + pr;
                    *reinterpret_cast<float2*>(pw + row * 516 + ng * 8 + pc) =
                        make_float2(acc[mg][ng][0], acc[mg][ng][1]);
                    *reinterpret_cast<float2*>(pw + (row + 8) * 516 + ng * 8 + pc) =
                        make_float2(acc[mg][ng][2], acc[mg][ng][3]);
                }
        }
        __syncthreads();   // barrier 1: partials visible; joins all chunk waits

        // reduce 8 warp-partials + cell update (thread: row eb, cols ejp*8+2g+e)
        {
            float2 gt[4];
#pragma unroll
            for (int gg = 0; gg < 4; gg++) {
                int c = ejp * 8 + 2 * gg;
                float2 s = make_float2(0.f, 0.f);
#pragma unroll
                for (int ww = 0; ww < 8; ww++) {
                    float2 v = *reinterpret_cast<const float2*>(
                        A_f + eb * 516 + ww * 64 + c);
                    s.x += v.x; s.y += v.y;
                }
                gt[gg] = s;
            }

            float iva = gt[0].x + xg[0].x;
            float ivb = gt[0].y + xg[0].y;
            float fva = gt[1].x + xg[1].x;
            float fvb = gt[1].y + xg[1].y;
            float gva = gt[2].x + xg[2].x;
            float gvb = gt[2].y + xg[2].y;
            float ova = gt[3].x + xg[3].x;
            float ovb = gt[3].y + xg[3].y;

            float cna = fast_sigmoid(fva) * creg.x + fast_sigmoid(iva) * fast_tanh(gva);
            float cnb = fast_sigmoid(fvb) * creg.y + fast_sigmoid(ivb) * fast_tanh(gvb);
            float hna = fast_sigmoid(ova) * fast_tanh(cna);
            float hnb = fast_sigmoid(ovb) * fast_tanh(cnb);
            creg.x = cna; creg.y = cnb;

            __half2 h2 = __floats2half2_rn(hna, hnb);
            *reinterpret_cast<__half2*>(
                h16 + (size_t)((t + 1) & 1) * BH + (size_t)bloc * H_ + j0 + 2 * ejp) = h2;
            *reinterpret_cast<__half2*>(
                ys16 + ((size_t)bloc * T_ + t) * (size_t)H_ + j0 + 2 * ejp) = h2;
        }

        // barrier 2: h-stores done + reduce-reads done (protects next-step
        // staging WAR on the slice region) -> single release per CTA-step
        __syncthreads();
        if (tid == 0) red_release_add(&cnt[(t * 2 + bh) * 4 + qself], 1);
    }

    // write back final cell state
    *reinterpret_cast<float2*>(cout + (size_t)bloc * H_ + j0 + 2 * ejp) = creg;
}

// ---------------------------------------------------------------------------
// fc2 split-K: z2(64,36) += z1(64,131072) @ W(131072,36); z2 pre-seeded w/ bias
// ---------------------------------------------------------------------------
constexpr int FC2_SMEM = 256 * 65 * 4 + 256 * 37 * 4;  // 104448

__global__ void __launch_bounds__(256) fc2_split(
    const float* __restrict__ z1, const float* __restrict__ W,
    float* __restrict__ z2)
{
    extern __shared__ float smf[];
    float* As = smf;                 // [256 k][65 m-pad]
    float* Ws = smf + 256 * 65;      // [256 k][37 n-pad]
    const int k0 = blockIdx.x * 256;
    const int tid = threadIdx.x;

    for (int i = 0; i < 16; i++) {
        int idx = tid + i * 256;
        int m = idx >> 6, kc = (idx & 63) * 4;
        float4 v = *reinterpret_cast<const float4*>(z1 + (size_t)m * 131072 + k0 + kc);
        As[(kc + 0) * 65 + m] = v.x;
        As[(kc + 1) * 65 + m] = v.y;
        As[(kc + 2) * 65 + m] = v.z;
        As[(kc + 3) * 65 + m] = v.w;
    }
    for (int i = 0; i < 36; i++) {
        int idx = tid + i * 256;
        int k = idx / 36, n = idx - k * 36;
        Ws[k * 37 + n] = W[(size_t)(k0 + k) * 36 + n];
    }
    __syncthreads();

    const int m = tid & 63, ng = tid >> 6;
    const int n0 = ng * 9;
    float acc[9];
#pragma unroll
    for (int j = 0; j < 9; j++) acc[j] = 0.f;

    for (int k = 0; k < 256; k++) {
        float a = As[k * 65 + m];
#pragma unroll
        for (int j = 0; j < 9; j++) acc[j] = fmaf(a, Ws[k * 37 + n0 + j], acc[j]);
    }
#pragma unroll
    for (int j = 0; j < 9; j++) atomicAdd(&z2[m * 36 + n0 + j], acc[j]);
}

__global__ void z2_init(const float* __restrict__ bias, float* __restrict__ z2)
{
    int i = blockIdx.x * 256 + threadIdx.x;
    if (i < B_ * 36) z2[i] = bias[i % 36];
}

// fc3 (36->6) + fc4 (6->6) + relu
__global__ void fc34_kernel(const float* __restrict__ z2,
                            const float* __restrict__ w3, const float* __restrict__ b3,
                            const float* __restrict__ w4, const float* __restrict__ b4,
                            float* __restrict__ out)
{
    int m = threadIdx.x;
    if (m >= B_) return;
    float t3[6];
#pragma unroll
    for (int n = 0; n < 6; n++) {
        float s = b3[n];
        for (int k = 0; k < 36; k++) s = fmaf(z2[m * 36 + k], w3[k * 6 + n], s);
        t3[n] = s;
    }
#pragma unroll
    for (int n = 0; n < 6; n++) {
        float s = b4[n];
#pragma unroll
        for (int k = 0; k < 6; k++) s = fmaf(t3[k], w4[k * 6 + n], s);
        out[m * 6 + n] = fmaxf(s, 0.f);
    }
}

// ---------------------------------------------------------------------------
extern "C" void kernel_launch(void* const* d_in, const int* in_sizes, int n_in,
                              void* d_out, int out_size)
{
    const float* x     = (const float*)d_in[0];
    const float* h0    = (const float*)d_in[1];
    const float* c0    = (const float*)d_in[2];
    const float* W1    = (const float*)d_in[3];
    const float* U1    = (const float*)d_in[4];
    const float* b1    = (const float*)d_in[5];
    const float* W2    = (const float*)d_in[6];
    const float* U2    = (const float*)d_in[7];
    const float* b2    = (const float*)d_in[8];
    const float* fc1_w = (const float*)d_in[9];
    const float* fc1_b = (const float*)d_in[10];
    const float* fc2_w = (const float*)d_in[11];
    const float* fc2_b = (const float*)d_in[12];
    const float* fc3_w = (const float*)d_in[13];
    const float* fc3_b = (const float*)d_in[14];
    const float* fc4_w = (const float*)d_in[15];
    const float* fc4_b = (const float*)d_in[16];
    float* out = (float*)d_out;

    float *xw, *c, *z1, *z2;
    int* cnt;
    __half *h16, *x16, *W1_16, *U1_16, *W2_16, *U2_16, *fc1w16, *ys1_16, *ys2_16;
    cudaGetSymbolAddress((void**)&xw, g_xw);
    cudaGetSymbolAddress((void**)&c, g_c);
    cudaGetSymbolAddress((void**)&h16, g_h16);
    cudaGetSymbolAddress((void**)&x16, g_x16);
    cudaGetSymbolAddress((void**)&W1_16, g_W1_16);
    cudaGetSymbolAddress((void**)&U1_16, g_U1_16);
    cudaGetSymbolAddress((void**)&W2_16, g_W2_16);
    cudaGetSymbolAddress((void**)&U2_16, g_U2_16);
    cudaGetSymbolAddress((void**)&fc1w16, g_fc1w16);
    cudaGetSymbolAddress((void**)&ys1_16, g_ys1_16);
    cudaGetSymbolAddress((void**)&ys2_16, g_ys2_16);
    cudaGetSymbolAddress((void**)&z1, g_z1);
    cudaGetSymbolAddress((void**)&z2, g_z2);
    cudaGetSymbolAddress((void**)&cnt, g_cnt);

    static bool attr_done = false;
    if (!attr_done) {
        cudaFuncSetAttribute(lstm_layer_tc11,
                             cudaFuncAttributeMaxDynamicSharedMemorySize, LSTM_SMEM);
        cudaFuncSetAttribute(fc2_split,
                             cudaFuncAttributeMaxDynamicSharedMemorySize, FC2_SMEM);
        attr_done = true;
    }

    const int MT = B_ * T_;  // 16384

    auto conv = [](const float* src, __half* dst, int n) {
        f32_to_f16<<<(n / 4 + 255) / 256, 256>>>(src, dst, n);
    };

    conv(x, x16, MT * D_);
    conv(W1, W1_16, D_ * G4);
    hgemm<<<dim3(G4 / 128, MT / 128), 256>>>(x16, W1_16, b1, xw, MT, G4, D_);
    conv(U1, U1_16, H_ * G4);
    init_all<<<BH / 256, 256>>>(h0, h16, cnt);
    lstm_layer_tc11<<<128, 256, LSTM_SMEM>>>(U1_16, xw, c0, c, h16, ys1_16, cnt);

    conv(W2, W2_16, H_ * G4);
    conv(U2, U2_16, H_ * G4);
    conv(fc1_w, fc1w16, H_ * (H_ / 2));

    // xw = ys1 @ W2 + b2
    hgemm<<<dim3(G4 / 128, MT / 128), 256>>>(ys1_16, W2_16, b2, xw, MT, G4, H_);

    // LSTM layer 2 (h16 buf0 / c carry over — matches reference seeding)
    lstm_layer_tc11<<<128, 256, LSTM_SMEM>>>(U2_16, xw, c, c, h16, ys2_16,
                                             cnt + T_ * 2 * 4);

    // z1 = ys2 @ fc1_w + fc1_b
    hgemm<<<dim3((H_ / 2) / 128, MT / 128), 256>>>(ys2_16, fc1w16, fc1_b, z1,
                                                   MT, H_ / 2, H_);

    // fc2: z2 = bias, then split-K accumulate
    z2_init<<<(B_ * 36 + 255) / 256, 256>>>(fc2_b, z2);
    fc2_split<<<512, 256, FC2_SMEM>>>(z1, fc2_w, z2);

    // fc3 + fc4 + relu -> out (64, 6)
    fc34_kernel<<<1, 64>>>(z2, fc3_w, fc3_b, fc4_w, fc4_b, out);
}